// round 11
// baseline (speedup 1.0000x reference)
#include <cuda_runtime.h>

// Problem constants (from reference setup_inputs)
#define N_NODES  100000
#define N_EDGES  1600000
#define PADN     102400           // 100 scan blocks x 1024
#define DIM      64
#define COUT     32
#define SCAN_BLK 100
#define SCAN_ELEMS 1024

#define GEMM_ROWS 128             // rows per block tile
#define AST_STRIDE 132            // padded row stride of transposed A (floats)
#define GEMM_SMEM ((64 * AST_STRIDE + 64 * 64) * 4)   // 50176 B
#define OUT_SMEM  ((64 * AST_STRIDE + 64 * 32) * 4)   // 41984 B

typedef unsigned long long u64;

// ---- packed f32x2 helpers (sm_103a FFMA2) ----------------------------------
__device__ __forceinline__ u64 f32x2_dup(float a) {
    u64 r;
    asm("mov.b64 %0, {%1, %1};" : "=l"(r) : "f"(a));
    return r;
}
__device__ __forceinline__ void f32x2_fma(u64& d, u64 a, u64 b) {
    asm("fma.rn.f32x2 %0, %1, %2, %0;" : "+l"(d) : "l"(a), "l"(b));
}
__device__ __forceinline__ float2 f32x2_unpack(u64 v) {
    float lo, hi;
    asm("mov.b64 {%0, %1}, %2;" : "=f"(lo), "=f"(hi) : "l"(v));
    return make_float2(lo, hi);
}

// ---------------------------------------------------------------------------
// Static device scratch (no cudaMalloc allowed)
// ---------------------------------------------------------------------------
__device__ int   g_deg_out[PADN];
__device__ int   g_deg_in[PADN];
__device__ int   g_sync;               // last-block-done counter (zeroed per call)
__device__ float g_norm_s[N_NODES];
__device__ float g_norm_d[N_NODES];
__device__ int   g_off[N_NODES + 1];   // local (per-scan-block) exclusive prefix
__device__ int   g_cursor[N_NODES];
__device__ int   g_bsum[SCAN_BLK];
__device__ int   g_boff[SCAN_BLK];     // exclusive prefix of block sums
// packed (src byte-offset, weight-bits) grouped by dst; +8 zero padding so
// aligned 8-edge batches can read past N_EDGES (zero-init, never written).
__device__ __align__(16) int2 g_edges[N_EDGES + 8];
__device__ float g_agg[N_NODES * DIM];
__device__ float g_hA[N_NODES * DIM];
__device__ float g_res[N_NODES * DIM];

// ---------------------------------------------------------------------------
// Prologue
// ---------------------------------------------------------------------------
__global__ void __launch_bounds__(256) k_count(const int* __restrict__ src,
                                               const int* __restrict__ dst) {
    int t = blockIdx.x * blockDim.x + threadIdx.x;
    if (t < N_EDGES / 4) {
        int4 s = ((const int4*)src)[t];
        int4 d = ((const int4*)dst)[t];
        atomicAdd(&g_deg_out[s.x], 1); atomicAdd(&g_deg_out[s.y], 1);
        atomicAdd(&g_deg_out[s.z], 1); atomicAdd(&g_deg_out[s.w], 1);
        atomicAdd(&g_deg_in[d.x], 1);  atomicAdd(&g_deg_in[d.y], 1);
        atomicAdd(&g_deg_in[d.z], 1);  atomicAdd(&g_deg_in[d.w], 1);
    }
}

// Per-block local exclusive scan of deg_in + norms; LAST block scans block sums.
__global__ void __launch_bounds__(256) k_scan_local() {
    __shared__ int wexcl[8];
    __shared__ int s_last;
    const int tid  = threadIdx.x;
    const int lane = tid & 31;
    const int wid  = tid >> 5;
    const int i0   = blockIdx.x * SCAN_ELEMS + tid * 4;

    int4 v = *((const int4*)(g_deg_in + i0));

    if (i0 < N_NODES) {   // N_NODES % 4 == 0
        int4 o = *((const int4*)(g_deg_out + i0));
        g_norm_d[i0 + 0] = rsqrtf((float)max(v.x, 1));
        g_norm_d[i0 + 1] = rsqrtf((float)max(v.y, 1));
        g_norm_d[i0 + 2] = rsqrtf((float)max(v.z, 1));
        g_norm_d[i0 + 3] = rsqrtf((float)max(v.w, 1));
        g_norm_s[i0 + 0] = rsqrtf((float)max(o.x, 1));
        g_norm_s[i0 + 1] = rsqrtf((float)max(o.y, 1));
        g_norm_s[i0 + 2] = rsqrtf((float)max(o.z, 1));
        g_norm_s[i0 + 3] = rsqrtf((float)max(o.w, 1));
    }

    int sum = v.x + v.y + v.z + v.w;
    int x = sum;
    #pragma unroll
    for (int o = 1; o < 32; o <<= 1) {
        int t = __shfl_up_sync(0xffffffffu, x, o);
        if (lane >= o) x += t;
    }
    if (lane == 31) wexcl[wid] = x;
    __syncthreads();
    if (wid == 0 && lane < 8) {
        int t = wexcl[lane];
        int y = t;
        #pragma unroll
        for (int o = 1; o < 8; o <<= 1) {
            int u = __shfl_up_sync(0xffu, y, o);
            if (lane >= o) y += u;
        }
        wexcl[lane] = y - t;
    }
    __syncthreads();

    int excl = (x - sum) + wexcl[wid];
    if (i0 < N_NODES) {
        int4 w;
        w.x = excl;
        w.y = excl + v.x;
        w.z = excl + v.x + v.y;
        w.w = excl + v.x + v.y + v.z;
        *((int4*)(g_off + i0))    = w;
        *((int4*)(g_cursor + i0)) = w;
    }
    if (tid == 255) g_bsum[blockIdx.x] = excl + sum;

    // ---- last finished block scans the 100 block sums -> g_boff ----
    __threadfence();
    if (tid == 0) s_last = (atomicAdd(&g_sync, 1) == SCAN_BLK - 1);
    __syncthreads();
    if (s_last && tid < 128) {
        __shared__ int wtot[4];
        int val = (tid < SCAN_BLK) ? g_bsum[tid] : 0;
        int xx = val;
        #pragma unroll
        for (int o = 1; o < 32; o <<= 1) {
            int t = __shfl_up_sync(0xffffffffu, xx, o);
            if (lane >= o) xx += t;
        }
        if (lane == 31) wtot[wid] = xx;
        __syncwarp();
        __syncthreads();
        int woff = 0;
        #pragma unroll
        for (int w = 0; w < 4; w++) if (w < wid) woff += wtot[w];
        if (tid < SCAN_BLK) g_boff[tid] = woff + xx - val;
    }
}

// Counting-sort scatter (4 edges/thread): pack (src byte-offset, ew*norm_s[src])
__global__ void __launch_bounds__(256) k_scatter(const int* __restrict__ src,
                                                 const int* __restrict__ dst,
                                                 const float* __restrict__ ew) {
    int t = blockIdx.x * blockDim.x + threadIdx.x;
    if (t < N_EDGES / 4) {
        int4   s = ((const int4*)src)[t];
        int4   d = ((const int4*)dst)[t];
        float4 w = ((const float4*)ew)[t];
        int p;
        p = atomicAdd(&g_cursor[d.x], 1) + g_boff[d.x >> 10];
        g_edges[p] = make_int2(s.x << 8, __float_as_int(w.x * g_norm_s[s.x]));
        p = atomicAdd(&g_cursor[d.y], 1) + g_boff[d.y >> 10];
        g_edges[p] = make_int2(s.y << 8, __float_as_int(w.y * g_norm_s[s.y]));
        p = atomicAdd(&g_cursor[d.z], 1) + g_boff[d.z >> 10];
        g_edges[p] = make_int2(s.z << 8, __float_as_int(w.z * g_norm_s[s.z]));
        p = atomicAdd(&g_cursor[d.w], 1) + g_boff[d.w >> 10];
        g_edges[p] = make_int2(s.w << 8, __float_as_int(w.w * g_norm_s[s.w]));
    }
}

// ---------------------------------------------------------------------------
// Aggregation: one warp per dst node, full warp per edge (float2 per lane).
// Aligned 8-edge batches: metas via 4x LDG.128; interior batches unmasked
// (warp-uniform branch), only boundary batches pay per-edge selects.
// ---------------------------------------------------------------------------
__global__ void __launch_bounds__(256) k_aggregate(const float* __restrict__ in,
                                                   float* __restrict__ outagg) {
    int gw = (blockIdx.x * blockDim.x + threadIdx.x) >> 5;
    if (gw >= N_NODES) return;
    const int lane = threadIdx.x & 31;

    const int beg = g_off[gw] + g_boff[gw >> 10];
    const int end = (gw + 1 == N_NODES) ? N_EDGES
                                        : g_off[gw + 1] + g_boff[(gw + 1) >> 10];

    if (beg >= end) {   // degree-0: agg = 0
        *((float2*)(outagg + (size_t)gw * DIM + lane * 2)) = make_float2(0.f, 0.f);
        return;
    }

    const char* base = (const char*)in + lane * 8;
    float ax[8], ay[8];
    #pragma unroll
    for (int j = 0; j < 8; j++) { ax[j] = 0.f; ay[j] = 0.f; }

    for (int e = beg & ~7; e < end; e += 8) {
        // metas: 64 consecutive bytes, 16B-aligned -> 4x LDG.128
        int4 q0 = *((const int4*)&g_edges[e]);      // edges e,   e+1
        int4 q1 = *((const int4*)&g_edges[e + 2]);  // edges e+2, e+3
        int4 q2 = *((const int4*)&g_edges[e + 4]);
        int4 q3 = *((const int4*)&g_edges[e + 6]);
        if (e >= beg && e + 8 <= end) {
            // interior batch: no masking at all
            float2 x0 = *((const float2*)(base + q0.x));
            float2 x1 = *((const float2*)(base + q0.z));
            float2 x2 = *((const float2*)(base + q1.x));
            float2 x3 = *((const float2*)(base + q1.z));
            float2 x4 = *((const float2*)(base + q2.x));
            float2 x5 = *((const float2*)(base + q2.z));
            float2 x6 = *((const float2*)(base + q3.x));
            float2 x7 = *((const float2*)(base + q3.z));
            float w0 = __int_as_float(q0.y), w1 = __int_as_float(q0.w);
            float w2 = __int_as_float(q1.y), w3 = __int_as_float(q1.w);
            float w4 = __int_as_float(q2.y), w5 = __int_as_float(q2.w);
            float w6 = __int_as_float(q3.y), w7 = __int_as_float(q3.w);
            ax[0] += x0.x * w0; ay[0] += x0.y * w0;
            ax[1] += x1.x * w1; ay[1] += x1.y * w1;
            ax[2] += x2.x * w2; ay[2] += x2.y * w2;
            ax[3] += x3.x * w3; ay[3] += x3.y * w3;
            ax[4] += x4.x * w4; ay[4] += x4.y * w4;
            ax[5] += x5.x * w5; ay[5] += x5.y * w5;
            ax[6] += x6.x * w6; ay[6] += x6.y * w6;
            ax[7] += x7.x * w7; ay[7] += x7.y * w7;
        } else {
            // boundary batch: mask weights outside [beg, end)
            int4 q[4] = {q0, q1, q2, q3};
            #pragma unroll
            for (int p = 0; p < 4; p++) {
                int i0 = e + 2 * p, i1 = i0 + 1;
                float w0 = (i0 >= beg && i0 < end) ? __int_as_float(q[p].y) : 0.f;
                float w1 = (i1 >= beg && i1 < end) ? __int_as_float(q[p].w) : 0.f;
                float2 xv0 = *((const float2*)(base + q[p].x));
                float2 xv1 = *((const float2*)(base + q[p].z));
                ax[2 * p]     += xv0.x * w0; ay[2 * p]     += xv0.y * w0;
                ax[2 * p + 1] += xv1.x * w1; ay[2 * p + 1] += xv1.y * w1;
            }
        }
    }

    float sx = ((ax[0] + ax[1]) + (ax[2] + ax[3])) + ((ax[4] + ax[5]) + (ax[6] + ax[7]));
    float sy = ((ay[0] + ay[1]) + (ay[2] + ay[3])) + ((ay[4] + ay[5]) + (ay[6] + ay[7]));

    float nd = g_norm_d[gw];
    float2 r;
    r.x = sx * nd;
    r.y = sy * nd;
    *((float2*)(outagg + (size_t)gw * DIM + lane * 2)) = r;
}

// ---------------------------------------------------------------------------
// Register-blocked SGEMM, outer product + packed FFMA2.
// Tile 128 rows x 64 cols, 128 threads, each thread 8 rows x 8 cols.
// Optional fused residual-add (+relu) in the epilogue.
// ---------------------------------------------------------------------------
template <bool RELU, bool ADDRES>
__global__ void __launch_bounds__(128, 4) k_gemm(const float* __restrict__ in,
                                                 const float* __restrict__ W,
                                                 const float* __restrict__ b,
                                                 const float* __restrict__ res,
                                                 float* __restrict__ out) {
    extern __shared__ float smem[];
    float* AsT = smem;                       // [64][AST_STRIDE]  (A transposed)
    float* Ws  = smem + 64 * AST_STRIDE;     // [64][64]

    const int tid  = threadIdx.x;            // 128 threads
    const int row0 = blockIdx.x * GEMM_ROWS;

    {
        const int r  = tid;
        const int gr = row0 + r;
        if (gr < N_NODES) {
            const float4* ap = (const float4*)(in + (size_t)gr * DIM);
            #pragma unroll
            for (int c4 = 0; c4 < 16; c4++) {
                float4 v = ap[c4];
                AsT[(c4 * 4 + 0) * AST_STRIDE + r] = v.x;
                AsT[(c4 * 4 + 1) * AST_STRIDE + r] = v.y;
                AsT[(c4 * 4 + 2) * AST_STRIDE + r] = v.z;
                AsT[(c4 * 4 + 3) * AST_STRIDE + r] = v.w;
            }
        } else {
            #pragma unroll
            for (int c = 0; c < 64; c++)
                AsT[c * AST_STRIDE + r] = 0.f;
        }
    }
    #pragma unroll
    for (int i = tid; i < 64 * 16; i += 128)
        ((float4*)Ws)[i] = ((const float4*)W)[i];
    __syncthreads();

    const int tx = tid & 7;                  // col group: cols tx*8 .. +7
    const int ty = tid >> 3;                 // row group: rows ty*8 .. +7

    u64 acc[4][8];                           // [row-pair][col]
    #pragma unroll
    for (int i = 0; i < 4; i++)
        #pragma unroll
        for (int j = 0; j < 8; j++) acc[i][j] = 0ull;

    #pragma unroll
    for (int k = 0; k < 64; k++) {
        ulonglong2 A0 = *((const ulonglong2*)&AsT[k * AST_STRIDE + ty * 8]);
        ulonglong2 A1 = *((const ulonglong2*)&AsT[k * AST_STRIDE + ty * 8 + 4]);
        u64 ap[4] = {A0.x, A0.y, A1.x, A1.y};
        float4 B0 = *((const float4*)&Ws[k * 64 + tx * 8]);
        float4 B1 = *((const float4*)&Ws[k * 64 + tx * 8 + 4]);
        u64 bd[8];
        bd[0] = f32x2_dup(B0.x); bd[1] = f32x2_dup(B0.y);
        bd[2] = f32x2_dup(B0.z); bd[3] = f32x2_dup(B0.w);
        bd[4] = f32x2_dup(B1.x); bd[5] = f32x2_dup(B1.y);
        bd[6] = f32x2_dup(B1.z); bd[7] = f32x2_dup(B1.w);
        #pragma unroll
        for (int i = 0; i < 4; i++)
            #pragma unroll
            for (int j = 0; j < 8; j++)
                f32x2_fma(acc[i][j], ap[i], bd[j]);
    }

    float4 bv0 = *((const float4*)(b + tx * 8));
    float4 bv1 = *((const float4*)(b + tx * 8 + 4));
    #pragma unroll
    for (int i2 = 0; i2 < 4; i2++) {
        float2 c0 = f32x2_unpack(acc[i2][0]);
        float2 c1 = f32x2_unpack(acc[i2][1]);
        float2 c2 = f32x2_unpack(acc[i2][2]);
        float2 c3 = f32x2_unpack(acc[i2][3]);
        float2 c4 = f32x2_unpack(acc[i2][4]);
        float2 c5 = f32x2_unpack(acc[i2][5]);
        float2 c6 = f32x2_unpack(acc[i2][6]);
        float2 c7 = f32x2_unpack(acc[i2][7]);
        #pragma unroll
        for (int h = 0; h < 2; h++) {
            int gr = row0 + ty * 8 + i2 * 2 + h;
            if (gr < N_NODES) {
                float4 o0, o1;
                o0.x = (h ? c0.y : c0.x) + bv0.x;
                o0.y = (h ? c1.y : c1.x) + bv0.y;
                o0.z = (h ? c2.y : c2.x) + bv0.z;
                o0.w = (h ? c3.y : c3.x) + bv0.w;
                o1.x = (h ? c4.y : c4.x) + bv1.x;
                o1.y = (h ? c5.y : c5.x) + bv1.y;
                o1.z = (h ? c6.y : c6.x) + bv1.z;
                o1.w = (h ? c7.y : c7.x) + bv1.w;
                if (ADDRES) {
                    const float* rr = res + (size_t)gr * DIM + tx * 8;
                    float4 r0 = *((const float4*)rr);
                    float4 r1 = *((const float4*)(rr + 4));
                    o0.x += r0.x; o0.y += r0.y; o0.z += r0.z; o0.w += r0.w;
                    o1.x += r1.x; o1.y += r1.y; o1.z += r1.z; o1.w += r1.w;
                }
                if (RELU) {
                    o0.x = fmaxf(o0.x, 0.f); o0.y = fmaxf(o0.y, 0.f);
                    o0.z = fmaxf(o0.z, 0.f); o0.w = fmaxf(o0.w, 0.f);
                    o1.x = fmaxf(o1.x, 0.f); o1.y = fmaxf(o1.y, 0.f);
                    o1.z = fmaxf(o1.z, 0.f); o1.w = fmaxf(o1.w, 0.f);
                }
                float* op = out + (size_t)gr * DIM + tx * 8;
                *((float4*)op)       = o0;
                *((float4*)(op + 4)) = o1;
            }
        }
    }
}

// ---------------------------------------------------------------------------
// Output projection: out[N,32] = in[N,64] @ Wo[64,32] + bo.
// ---------------------------------------------------------------------------
__global__ void __launch_bounds__(128, 4) k_gemm_out(const float* __restrict__ in,
                                                     const float* __restrict__ Wo,
                                                     const float* __restrict__ bo,
                                                     float* __restrict__ out) {
    extern __shared__ float smem[];
    float* AsT = smem;                       // [64][AST_STRIDE]
    float* Ws  = smem + 64 * AST_STRIDE;     // [64][32]

    const int tid  = threadIdx.x;
    const int row0 = blockIdx.x * GEMM_ROWS;

    {
        const int r  = tid;
        const int gr = row0 + r;
        if (gr < N_NODES) {
            const float4* ap = (const float4*)(in + (size_t)gr * DIM);
            #pragma unroll
            for (int c4 = 0; c4 < 16; c4++) {
                float4 v = ap[c4];
                AsT[(c4 * 4 + 0) * AST_STRIDE + r] = v.x;
                AsT[(c4 * 4 + 1) * AST_STRIDE + r] = v.y;
                AsT[(c4 * 4 + 2) * AST_STRIDE + r] = v.z;
                AsT[(c4 * 4 + 3) * AST_STRIDE + r] = v.w;
            }
        } else {
            #pragma unroll
            for (int c = 0; c < 64; c++)
                AsT[c * AST_STRIDE + r] = 0.f;
        }
    }
    #pragma unroll
    for (int i = tid; i < 64 * 8; i += 128)
        ((float4*)Ws)[i] = ((const float4*)Wo)[i];
    __syncthreads();

    const int tx = tid & 7;                  // col group: cols tx*4 .. +3
    const int ty = tid >> 3;                 // row group: rows ty*8 .. +7

    u64 acc[4][4];                           // [row-pair][col]
    #pragma unroll
    for (int i = 0; i < 4; i++)
        #pragma unroll
        for (int j = 0; j < 4; j++) acc[i][j] = 0ull;

    #pragma unroll
    for (int k = 0; k < 64; k++) {
        ulonglong2 A0 = *((const ulonglong2*)&AsT[k * AST_STRIDE + ty * 8]);
        ulonglong2 A1 = *((const ulonglong2*)&AsT[k * AST_STRIDE + ty * 8 + 4]);
        u64 ap[4] = {A0.x, A0.y, A1.x, A1.y};
        float4 B0 = *((const float4*)&Ws[k * 32 + tx * 4]);
        u64 bd[4];
        bd[0] = f32x2_dup(B0.x); bd[1] = f32x2_dup(B0.y);
        bd[2] = f32x2_dup(B0.z); bd[3] = f32x2_dup(B0.w);
        #pragma unroll
        for (int i = 0; i < 4; i++)
            #pragma unroll
            for (int j = 0; j < 4; j++)
                f32x2_fma(acc[i][j], ap[i], bd[j]);
    }

    float4 bv = *((const float4*)(bo + tx * 4));
    #pragma unroll
    for (int i2 = 0; i2 < 4; i2++) {
        float2 c0 = f32x2_unpack(acc[i2][0]);
        float2 c1 = f32x2_unpack(acc[i2][1]);
        float2 c2 = f32x2_unpack(acc[i2][2]);
        float2 c3 = f32x2_unpack(acc[i2][3]);
        #pragma unroll
        for (int h = 0; h < 2; h++) {
            int gr = row0 + ty * 8 + i2 * 2 + h;
            if (gr < N_NODES) {
                float4 o;
                o.x = (h ? c0.y : c0.x) + bv.x;
                o.y = (h ? c1.y : c1.x) + bv.y;
                o.z = (h ? c2.y : c2.x) + bv.z;
                o.w = (h ? c3.y : c3.x) + bv.w;
                *((float4*)(out + (size_t)gr * COUT + tx * 4)) = o;
            }
        }
    }
}

// ---------------------------------------------------------------------------
// Launch
// ---------------------------------------------------------------------------
extern "C" void kernel_launch(void* const* d_in, const int* in_sizes, int n_in,
                              void* d_out, int out_size) {
    const float* x   = (const float*)d_in[0];
    const int*   src = (const int*)d_in[1];
    const int*   dst = (const int*)d_in[2];
    const float* ew  = (const float*)d_in[3];
    const float* W1 = (const float*)d_in[4];
    const float* b1 = (const float*)d_in[5];
    const float* W2 = (const float*)d_in[6];
    const float* b2 = (const float*)d_in[7];
    const float* W3 = (const float*)d_in[8];
    const float* b3 = (const float*)d_in[9];
    const float* W4 = (const float*)d_in[10];
    const float* b4 = (const float*)d_in[11];
    const float* Wr = (const float*)d_in[12];
    const float* br = (const float*)d_in[13];
    const float* Wo = (const float*)d_in[14];
    const float* bo = (const float*)d_in[15];
    float* out = (float*)d_out;

    float* agg; cudaGetSymbolAddress((void**)&agg, g_agg);
    float* hA;  cudaGetSymbolAddress((void**)&hA,  g_hA);
    float* res; cudaGetSymbolAddress((void**)&res, g_res);
    int* degout; cudaGetSymbolAddress((void**)&degout, g_deg_out);
    int* degin;  cudaGetSymbolAddress((void**)&degin,  g_deg_in);
    int* syncp;  cudaGetSymbolAddress((void**)&syncp,  g_sync);

    cudaFuncSetAttribute(k_gemm<false,false>, cudaFuncAttributeMaxDynamicSharedMemorySize, GEMM_SMEM);
    cudaFuncSetAttribute(k_gemm<true,false>,  cudaFuncAttributeMaxDynamicSharedMemorySize, GEMM_SMEM);
    cudaFuncSetAttribute(k_gemm<true,true>,   cudaFuncAttributeMaxDynamicSharedMemorySize, GEMM_SMEM);
    cudaFuncSetAttribute(k_gemm_out,          cudaFuncAttributeMaxDynamicSharedMemorySize, OUT_SMEM);

    const int TPB = 256;
    const int gE4 = (N_EDGES / 4 + TPB - 1) / TPB;
    const int gAgg   = (N_NODES * 32 + TPB - 1) / TPB;           // warp per node
    const int gGemm  = (N_NODES + GEMM_ROWS - 1) / GEMM_ROWS;    // 782
    const int TG = 128;

    cudaMemsetAsync(degout, 0, PADN * sizeof(int));
    cudaMemsetAsync(degin,  0, PADN * sizeof(int));
    cudaMemsetAsync(syncp,  0, sizeof(int));

    k_count<<<gE4, TPB>>>(src, dst);                 // launch 0
    k_scan_local<<<SCAN_BLK, 256>>>();               // launch 1 (incl. bsum scan)
    k_scatter<<<gE4, TPB>>>(src, dst, ew);           // launch 2

    // Layer 1 aggregate — launch 3 (ncu capture slot)
    k_aggregate<<<gAgg, TPB>>>(x, agg);
    // Residual GEMM (independent; only needs x)
    k_gemm<false,false><<<gGemm, TG, GEMM_SMEM>>>(x, Wr, br, nullptr, res);
    k_gemm<true,false><<<gGemm, TG, GEMM_SMEM>>>(agg, W1, b1, nullptr, hA);

    // Layers 2-3
    k_aggregate<<<gAgg, TPB>>>(hA, agg);
    k_gemm<true,false><<<gGemm, TG, GEMM_SMEM>>>(agg, W2, b2, nullptr, hA);
    k_aggregate<<<gAgg, TPB>>>(hA, agg);
    k_gemm<true,false><<<gGemm, TG, GEMM_SMEM>>>(agg, W3, b3, nullptr, hA);

    // Layer 4: aggregate, gemm with fused residual+relu, output projection
    k_aggregate<<<gAgg, TPB>>>(hA, agg);
    k_gemm<true,true><<<gGemm, TG, GEMM_SMEM>>>(agg, W4, b4, res, hA);
    k_gemm_out<<<gGemm, TG, OUT_SMEM>>>(hA, Wo, bo, out);
}

// round 12
// speedup vs baseline: 1.3796x; 1.3796x over previous
#include <cuda_runtime.h>
#include <cuda_fp16.h>

// Problem constants (from reference setup_inputs)
#define N_NODES  100000
#define N_EDGES  1600000
#define PADN     102400           // 100 scan blocks x 1024
#define DIM      64
#define COUT     32
#define SCAN_BLK 100
#define SCAN_ELEMS 1024

#define GEMM_ROWS 128             // rows per block tile
#define AST_STRIDE 132            // padded row stride of transposed A (floats)
#define GEMM_SMEM ((64 * AST_STRIDE + 64 * 64) * 4)   // 50176 B
#define OUT_SMEM  ((64 * AST_STRIDE + 64 * 32) * 4)   // 41984 B

typedef unsigned long long u64;

// ---- packed f32x2 helpers (sm_103a FFMA2) ----------------------------------
__device__ __forceinline__ u64 f32x2_dup(float a) {
    u64 r;
    asm("mov.b64 %0, {%1, %1};" : "=l"(r) : "f"(a));
    return r;
}
__device__ __forceinline__ void f32x2_fma(u64& d, u64 a, u64 b) {
    asm("fma.rn.f32x2 %0, %1, %2, %0;" : "+l"(d) : "l"(a), "l"(b));
}
__device__ __forceinline__ float2 f32x2_unpack(u64 v) {
    float lo, hi;
    asm("mov.b64 {%0, %1}, %2;" : "=f"(lo), "=f"(hi) : "l"(v));
    return make_float2(lo, hi);
}
__device__ __forceinline__ unsigned h2bits(__half2 h) {
    return *(unsigned*)&h;
}

// ---------------------------------------------------------------------------
// Static device scratch (no cudaMalloc allowed)
// ---------------------------------------------------------------------------
__device__ int    g_deg_out[PADN];
__device__ int    g_deg_in[PADN];
__device__ int    g_sync;              // last-block-done counter (zeroed per call)
__device__ float  g_norm_s[N_NODES];
__device__ float  g_norm_d[N_NODES];
__device__ int    g_off[N_NODES + 1];  // local (per-scan-block) exclusive prefix
__device__ int    g_cursor[N_NODES];
__device__ int    g_bsum[SCAN_BLK];
__device__ int    g_boff[SCAN_BLK];    // exclusive prefix of block sums
__device__ __align__(16) int2 g_edges[N_EDGES];  // (src byte-offset(fp16 row), w)
__device__ float  g_agg[N_NODES * DIM];
__device__ float  g_hA[N_NODES * DIM];
__device__ float  g_res[N_NODES * DIM];
__device__ __align__(16) __half g_h16[N_NODES * DIM];  // fp16 gather source

// ---------------------------------------------------------------------------
// Prologue: degree count (4 edges/thread) + x -> fp16 conversion (8 elems/thr)
// ---------------------------------------------------------------------------
__global__ void __launch_bounds__(256) k_prep(const float* __restrict__ x,
                                              const int* __restrict__ src,
                                              const int* __restrict__ dst) {
    int t = blockIdx.x * blockDim.x + threadIdx.x;
    if (t < N_NODES * DIM / 8) {
        float4 a = ((const float4*)x)[2 * t];
        float4 b = ((const float4*)x)[2 * t + 1];
        uint4 u;
        u.x = h2bits(__floats2half2_rn(a.x, a.y));
        u.y = h2bits(__floats2half2_rn(a.z, a.w));
        u.z = h2bits(__floats2half2_rn(b.x, b.y));
        u.w = h2bits(__floats2half2_rn(b.z, b.w));
        ((uint4*)g_h16)[t] = u;
    }
    if (t < N_EDGES / 4) {
        int4 s = ((const int4*)src)[t];
        int4 d = ((const int4*)dst)[t];
        atomicAdd(&g_deg_out[s.x], 1); atomicAdd(&g_deg_out[s.y], 1);
        atomicAdd(&g_deg_out[s.z], 1); atomicAdd(&g_deg_out[s.w], 1);
        atomicAdd(&g_deg_in[d.x], 1);  atomicAdd(&g_deg_in[d.y], 1);
        atomicAdd(&g_deg_in[d.z], 1);  atomicAdd(&g_deg_in[d.w], 1);
    }
}

// Per-block local exclusive scan of deg_in + norms; LAST block scans block sums.
__global__ void __launch_bounds__(256) k_scan_local() {
    __shared__ int wexcl[8];
    __shared__ int s_last;
    const int tid  = threadIdx.x;
    const int lane = tid & 31;
    const int wid  = tid >> 5;
    const int i0   = blockIdx.x * SCAN_ELEMS + tid * 4;

    int4 v = *((const int4*)(g_deg_in + i0));

    if (i0 < N_NODES) {   // N_NODES % 4 == 0
        int4 o = *((const int4*)(g_deg_out + i0));
        g_norm_d[i0 + 0] = rsqrtf((float)max(v.x, 1));
        g_norm_d[i0 + 1] = rsqrtf((float)max(v.y, 1));
        g_norm_d[i0 + 2] = rsqrtf((float)max(v.z, 1));
        g_norm_d[i0 + 3] = rsqrtf((float)max(v.w, 1));
        g_norm_s[i0 + 0] = rsqrtf((float)max(o.x, 1));
        g_norm_s[i0 + 1] = rsqrtf((float)max(o.y, 1));
        g_norm_s[i0 + 2] = rsqrtf((float)max(o.z, 1));
        g_norm_s[i0 + 3] = rsqrtf((float)max(o.w, 1));
    }

    int sum = v.x + v.y + v.z + v.w;
    int x = sum;
    #pragma unroll
    for (int o = 1; o < 32; o <<= 1) {
        int t = __shfl_up_sync(0xffffffffu, x, o);
        if (lane >= o) x += t;
    }
    if (lane == 31) wexcl[wid] = x;
    __syncthreads();
    if (wid == 0 && lane < 8) {
        int t = wexcl[lane];
        int y = t;
        #pragma unroll
        for (int o = 1; o < 8; o <<= 1) {
            int u = __shfl_up_sync(0xffu, y, o);
            if (lane >= o) y += u;
        }
        wexcl[lane] = y - t;
    }
    __syncthreads();

    int excl = (x - sum) + wexcl[wid];
    if (i0 < N_NODES) {
        int4 w;
        w.x = excl;
        w.y = excl + v.x;
        w.z = excl + v.x + v.y;
        w.w = excl + v.x + v.y + v.z;
        *((int4*)(g_off + i0))    = w;
        *((int4*)(g_cursor + i0)) = w;
    }
    if (tid == 255) g_bsum[blockIdx.x] = excl + sum;

    // ---- last finished block scans the 100 block sums -> g_boff ----
    __threadfence();
    if (tid == 0) s_last = (atomicAdd(&g_sync, 1) == SCAN_BLK - 1);
    __syncthreads();
    if (s_last && tid < 128) {
        __shared__ int wtot[4];
        int val = (tid < SCAN_BLK) ? g_bsum[tid] : 0;
        int xx = val;
        #pragma unroll
        for (int o = 1; o < 32; o <<= 1) {
            int t = __shfl_up_sync(0xffffffffu, xx, o);
            if (lane >= o) xx += t;
        }
        if (lane == 31) wtot[wid] = xx;
        __syncwarp();
        __syncthreads();
        int woff = 0;
        #pragma unroll
        for (int w = 0; w < 4; w++) if (w < wid) woff += wtot[w];
        if (tid < SCAN_BLK) g_boff[tid] = woff + xx - val;
    }
}

// Counting-sort scatter (4 edges/thread): pack (src byte-offset in fp16 rows
// = src*128, ew*norm_s[src]) grouped by dst.
__global__ void __launch_bounds__(256) k_scatter(const int* __restrict__ src,
                                                 const int* __restrict__ dst,
                                                 const float* __restrict__ ew) {
    int t = blockIdx.x * blockDim.x + threadIdx.x;
    if (t < N_EDGES / 4) {
        int4   s = ((const int4*)src)[t];
        int4   d = ((const int4*)dst)[t];
        float4 w = ((const float4*)ew)[t];
        int p;
        p = atomicAdd(&g_cursor[d.x], 1) + g_boff[d.x >> 10];
        g_edges[p] = make_int2(s.x << 7, __float_as_int(w.x * g_norm_s[s.x]));
        p = atomicAdd(&g_cursor[d.y], 1) + g_boff[d.y >> 10];
        g_edges[p] = make_int2(s.y << 7, __float_as_int(w.y * g_norm_s[s.y]));
        p = atomicAdd(&g_cursor[d.z], 1) + g_boff[d.z >> 10];
        g_edges[p] = make_int2(s.z << 7, __float_as_int(w.z * g_norm_s[s.z]));
        p = atomicAdd(&g_cursor[d.w], 1) + g_boff[d.w >> 10];
        g_edges[p] = make_int2(s.w << 7, __float_as_int(w.w * g_norm_s[s.w]));
    }
}

// ---------------------------------------------------------------------------
// Aggregation: one warp per dst node, full warp per edge (half2 per lane ->
// 128B/row gather), 8 edges in flight, fp32 accumulate. (R9 loop structure.)
// ---------------------------------------------------------------------------
__global__ void __launch_bounds__(256) k_aggregate(const __half* __restrict__ in,
                                                   float* __restrict__ outagg) {
    int gw = (blockIdx.x * blockDim.x + threadIdx.x) >> 5;
    if (gw >= N_NODES) return;
    const int lane = threadIdx.x & 31;

    const int beg = g_off[gw] + g_boff[gw >> 10];
    const int end = (gw + 1 == N_NODES) ? N_EDGES
                                        : g_off[gw + 1] + g_boff[(gw + 1) >> 10];

    if (beg >= end) {   // degree-0: agg = 0
        *((float2*)(outagg + (size_t)gw * DIM + lane * 2)) = make_float2(0.f, 0.f);
        return;
    }

    const char* base = (const char*)in + lane * 4;   // half2 = cols 2*lane..+1
    float ax[8], ay[8];
    #pragma unroll
    for (int j = 0; j < 8; j++) { ax[j] = 0.f; ay[j] = 0.f; }

    int e = beg;
    const int nfull = (end - beg) & ~7;
    for (; e < beg + nfull; e += 8) {
        int2 ed[8];
        #pragma unroll
        for (int j = 0; j < 8; j++) ed[j] = g_edges[e + j];   // warp-uniform bcast
        #pragma unroll
        for (int j = 0; j < 8; j++) {
            float  w  = __int_as_float(ed[j].y);
            float2 xv = __half22float2(*((const __half2*)(base + ed[j].x)));
            ax[j] += xv.x * w;
            ay[j] += xv.y * w;
        }
    }
    if (e < end) {                       // parallel clamped tail (1..7 edges)
        #pragma unroll
        for (int j = 0; j < 8; j++) {
            int  idx = min(e + j, end - 1);
            int2 ed  = g_edges[idx];
            float w  = (e + j < end) ? __int_as_float(ed.y) : 0.f;
            float2 xv = __half22float2(*((const __half2*)(base + ed.x)));
            ax[j] += xv.x * w;
            ay[j] += xv.y * w;
        }
    }

    float sx = ((ax[0] + ax[1]) + (ax[2] + ax[3])) + ((ax[4] + ax[5]) + (ax[6] + ax[7]));
    float sy = ((ay[0] + ay[1]) + (ay[2] + ay[3])) + ((ay[4] + ay[5]) + (ay[6] + ay[7]));

    float nd = g_norm_d[gw];
    float2 r;
    r.x = sx * nd;
    r.y = sy * nd;
    *((float2*)(outagg + (size_t)gw * DIM + lane * 2)) = r;
}

// ---------------------------------------------------------------------------
// Register-blocked SGEMM, outer product + packed FFMA2.
// Tile 128 rows x 64 cols, 128 threads, each thread 8 rows x 8 cols.
// HALFOUT: write fp16 (for the next layer's gather); else fp32.
// ADDRES: fused residual add. RELU: fused relu.
// ---------------------------------------------------------------------------
template <bool RELU, bool ADDRES, bool HALFOUT>
__global__ void __launch_bounds__(128, 4) k_gemm(const float* __restrict__ in,
                                                 const float* __restrict__ W,
                                                 const float* __restrict__ b,
                                                 const float* __restrict__ res,
                                                 void* __restrict__ outv) {
    extern __shared__ float smem[];
    float* AsT = smem;                       // [64][AST_STRIDE]  (A transposed)
    float* Ws  = smem + 64 * AST_STRIDE;     // [64][64]

    const int tid  = threadIdx.x;            // 128 threads
    const int row0 = blockIdx.x * GEMM_ROWS;

    {
        const int r  = tid;
        const int gr = row0 + r;
        if (gr < N_NODES) {
            const float4* ap = (const float4*)(in + (size_t)gr * DIM);
            #pragma unroll
            for (int c4 = 0; c4 < 16; c4++) {
                float4 v = ap[c4];
                AsT[(c4 * 4 + 0) * AST_STRIDE + r] = v.x;
                AsT[(c4 * 4 + 1) * AST_STRIDE + r] = v.y;
                AsT[(c4 * 4 + 2) * AST_STRIDE + r] = v.z;
                AsT[(c4 * 4 + 3) * AST_STRIDE + r] = v.w;
            }
        } else {
            #pragma unroll
            for (int c = 0; c < 64; c++)
                AsT[c * AST_STRIDE + r] = 0.f;
        }
    }
    #pragma unroll
    for (int i = tid; i < 64 * 16; i += 128)
        ((float4*)Ws)[i] = ((const float4*)W)[i];
    __syncthreads();

    const int tx = tid & 7;                  // col group: cols tx*8 .. +7
    const int ty = tid >> 3;                 // row group: rows ty*8 .. +7

    u64 acc[4][8];                           // [row-pair][col]
    #pragma unroll
    for (int i = 0; i < 4; i++)
        #pragma unroll
        for (int j = 0; j < 8; j++) acc[i][j] = 0ull;

    #pragma unroll
    for (int k = 0; k < 64; k++) {
        ulonglong2 A0 = *((const ulonglong2*)&AsT[k * AST_STRIDE + ty * 8]);
        ulonglong2 A1 = *((const ulonglong2*)&AsT[k * AST_STRIDE + ty * 8 + 4]);
        u64 ap[4] = {A0.x, A0.y, A1.x, A1.y};
        float4 B0 = *((const float4*)&Ws[k * 64 + tx * 8]);
        float4 B1 = *((const float4*)&Ws[k * 64 + tx * 8 + 4]);
        u64 bd[8];
        bd[0] = f32x2_dup(B0.x); bd[1] = f32x2_dup(B0.y);
        bd[2] = f32x2_dup(B0.z); bd[3] = f32x2_dup(B0.w);
        bd[4] = f32x2_dup(B1.x); bd[5] = f32x2_dup(B1.y);
        bd[6] = f32x2_dup(B1.z); bd[7] = f32x2_dup(B1.w);
        #pragma unroll
        for (int i = 0; i < 4; i++)
            #pragma unroll
            for (int j = 0; j < 8; j++)
                f32x2_fma(acc[i][j], ap[i], bd[j]);
    }

    float4 bv0 = *((const float4*)(b + tx * 8));
    float4 bv1 = *((const float4*)(b + tx * 8 + 4));
    #pragma unroll
    for (int i2 = 0; i2 < 4; i2++) {
        float2 c0 = f32x2_unpack(acc[i2][0]);
        float2 c1 = f32x2_unpack(acc[i2][1]);
        float2 c2 = f32x2_unpack(acc[i2][2]);
        float2 c3 = f32x2_unpack(acc[i2][3]);
        float2 c4 = f32x2_unpack(acc[i2][4]);
        float2 c5 = f32x2_unpack(acc[i2][5]);
        float2 c6 = f32x2_unpack(acc[i2][6]);
        float2 c7 = f32x2_unpack(acc[i2][7]);
        #pragma unroll
        for (int h = 0; h < 2; h++) {
            int gr = row0 + ty * 8 + i2 * 2 + h;
            if (gr < N_NODES) {
                float4 o0, o1;
                o0.x = (h ? c0.y : c0.x) + bv0.x;
                o0.y = (h ? c1.y : c1.x) + bv0.y;
                o0.z = (h ? c2.y : c2.x) + bv0.z;
                o0.w = (h ? c3.y : c3.x) + bv0.w;
                o1.x = (h ? c4.y : c4.x) + bv1.x;
                o1.y = (h ? c5.y : c5.x) + bv1.y;
                o1.z = (h ? c6.y : c6.x) + bv1.z;
                o1.w = (h ? c7.y : c7.x) + bv1.w;
                if (ADDRES) {
                    const float* rr = res + (size_t)gr * DIM + tx * 8;
                    float4 r0 = *((const float4*)rr);
                    float4 r1 = *((const float4*)(rr + 4));
                    o0.x += r0.x; o0.y += r0.y; o0.z += r0.z; o0.w += r0.w;
                    o1.x += r1.x; o1.y += r1.y; o1.z += r1.z; o1.w += r1.w;
                }
                if (RELU) {
                    o0.x = fmaxf(o0.x, 0.f); o0.y = fmaxf(o0.y, 0.f);
                    o0.z = fmaxf(o0.z, 0.f); o0.w = fmaxf(o0.w, 0.f);
                    o1.x = fmaxf(o1.x, 0.f); o1.y = fmaxf(o1.y, 0.f);
                    o1.z = fmaxf(o1.z, 0.f); o1.w = fmaxf(o1.w, 0.f);
                }
                if (HALFOUT) {
                    uint4 u;
                    u.x = h2bits(__floats2half2_rn(o0.x, o0.y));
                    u.y = h2bits(__floats2half2_rn(o0.z, o0.w));
                    u.z = h2bits(__floats2half2_rn(o1.x, o1.y));
                    u.w = h2bits(__floats2half2_rn(o1.z, o1.w));
                    *((uint4*)((__half*)outv + (size_t)gr * DIM + tx * 8)) = u;
                } else {
                    float* op = (float*)outv + (size_t)gr * DIM + tx * 8;
                    *((float4*)op)       = o0;
                    *((float4*)(op + 4)) = o1;
                }
            }
        }
    }
}

// ---------------------------------------------------------------------------
// Output projection: out[N,32] = in[N,64] @ Wo[64,32] + bo.
// ---------------------------------------------------------------------------
__global__ void __launch_bounds__(128, 4) k_gemm_out(const float* __restrict__ in,
                                                     const float* __restrict__ Wo,
                                                     const float* __restrict__ bo,
                                                     float* __restrict__ out) {
    extern __shared__ float smem[];
    float* AsT = smem;                       // [64][AST_STRIDE]
    float* Ws  = smem + 64 * AST_STRIDE;     // [64][32]

    const int tid  = threadIdx.x;
    const int row0 = blockIdx.x * GEMM_ROWS;

    {
        const int r  = tid;
        const int gr = row0 + r;
        if (gr < N_NODES) {
            const float4* ap = (const float4*)(in + (size_t)gr * DIM);
            #pragma unroll
            for (int c4 = 0; c4 < 16; c4++) {
                float4 v = ap[c4];
                AsT[(c4 * 4 + 0) * AST_STRIDE + r] = v.x;
                AsT[(c4 * 4 + 1) * AST_STRIDE + r] = v.y;
                AsT[(c4 * 4 + 2) * AST_STRIDE + r] = v.z;
                AsT[(c4 * 4 + 3) * AST_STRIDE + r] = v.w;
            }
        } else {
            #pragma unroll
            for (int c = 0; c < 64; c++)
                AsT[c * AST_STRIDE + r] = 0.f;
        }
    }
    #pragma unroll
    for (int i = tid; i < 64 * 8; i += 128)
        ((float4*)Ws)[i] = ((const float4*)Wo)[i];
    __syncthreads();

    const int tx = tid & 7;                  // col group: cols tx*4 .. +3
    const int ty = tid >> 3;                 // row group: rows ty*8 .. +7

    u64 acc[4][4];                           // [row-pair][col]
    #pragma unroll
    for (int i = 0; i < 4; i++)
        #pragma unroll
        for (int j = 0; j < 4; j++) acc[i][j] = 0ull;

    #pragma unroll
    for (int k = 0; k < 64; k++) {
        ulonglong2 A0 = *((const ulonglong2*)&AsT[k * AST_STRIDE + ty * 8]);
        ulonglong2 A1 = *((const ulonglong2*)&AsT[k * AST_STRIDE + ty * 8 + 4]);
        u64 ap[4] = {A0.x, A0.y, A1.x, A1.y};
        float4 B0 = *((const float4*)&Ws[k * 32 + tx * 4]);
        u64 bd[4];
        bd[0] = f32x2_dup(B0.x); bd[1] = f32x2_dup(B0.y);
        bd[2] = f32x2_dup(B0.z); bd[3] = f32x2_dup(B0.w);
        #pragma unroll
        for (int i = 0; i < 4; i++)
            #pragma unroll
            for (int j = 0; j < 4; j++)
                f32x2_fma(acc[i][j], ap[i], bd[j]);
    }

    float4 bv = *((const float4*)(bo + tx * 4));
    #pragma unroll
    for (int i2 = 0; i2 < 4; i2++) {
        float2 c0 = f32x2_unpack(acc[i2][0]);
        float2 c1 = f32x2_unpack(acc[i2][1]);
        float2 c2 = f32x2_unpack(acc[i2][2]);
        float2 c3 = f32x2_unpack(acc[i2][3]);
        #pragma unroll
        for (int h = 0; h < 2; h++) {
            int gr = row0 + ty * 8 + i2 * 2 + h;
            if (gr < N_NODES) {
                float4 o;
                o.x = (h ? c0.y : c0.x) + bv.x;
                o.y = (h ? c1.y : c1.x) + bv.y;
                o.z = (h ? c2.y : c2.x) + bv.z;
                o.w = (h ? c3.y : c3.x) + bv.w;
                *((float4*)(out + (size_t)gr * COUT + tx * 4)) = o;
            }
        }
    }
}

// ---------------------------------------------------------------------------
// Launch
// ---------------------------------------------------------------------------
extern "C" void kernel_launch(void* const* d_in, const int* in_sizes, int n_in,
                              void* d_out, int out_size) {
    const float* x   = (const float*)d_in[0];
    const int*   src = (const int*)d_in[1];
    const int*   dst = (const int*)d_in[2];
    const float* ew  = (const float*)d_in[3];
    const float* W1 = (const float*)d_in[4];
    const float* b1 = (const float*)d_in[5];
    const float* W2 = (const float*)d_in[6];
    const float* b2 = (const float*)d_in[7];
    const float* W3 = (const float*)d_in[8];
    const float* b3 = (const float*)d_in[9];
    const float* W4 = (const float*)d_in[10];
    const float* b4 = (const float*)d_in[11];
    const float* Wr = (const float*)d_in[12];
    const float* br = (const float*)d_in[13];
    const float* Wo = (const float*)d_in[14];
    const float* bo = (const float*)d_in[15];
    float* out = (float*)d_out;

    float*  agg; cudaGetSymbolAddress((void**)&agg, g_agg);
    float*  hA;  cudaGetSymbolAddress((void**)&hA,  g_hA);
    float*  res; cudaGetSymbolAddress((void**)&res, g_res);
    __half* h16; cudaGetSymbolAddress((void**)&h16, g_h16);
    int* degout; cudaGetSymbolAddress((void**)&degout, g_deg_out);
    int* degin;  cudaGetSymbolAddress((void**)&degin,  g_deg_in);
    int* syncp;  cudaGetSymbolAddress((void**)&syncp,  g_sync);

    cudaFuncSetAttribute(k_gemm<false,false,false>, cudaFuncAttributeMaxDynamicSharedMemorySize, GEMM_SMEM);
    cudaFuncSetAttribute(k_gemm<true,false,true>,   cudaFuncAttributeMaxDynamicSharedMemorySize, GEMM_SMEM);
    cudaFuncSetAttribute(k_gemm<true,true,false>,   cudaFuncAttributeMaxDynamicSharedMemorySize, GEMM_SMEM);
    cudaFuncSetAttribute(k_gemm_out,                cudaFuncAttributeMaxDynamicSharedMemorySize, OUT_SMEM);

    const int TPB = 256;
    const int gE4  = (N_EDGES / 4 + TPB - 1) / TPB;
    const int gPrep = (N_NODES * DIM / 8 + TPB - 1) / TPB;       // 3125 (>= gE4)
    const int gAgg  = (N_NODES * 32 + TPB - 1) / TPB;            // warp per node
    const int gGemm = (N_NODES + GEMM_ROWS - 1) / GEMM_ROWS;     // 782
    const int TG = 128;

    cudaMemsetAsync(degout, 0, PADN * sizeof(int));
    cudaMemsetAsync(degin,  0, PADN * sizeof(int));
    cudaMemsetAsync(syncp,  0, sizeof(int));

    k_prep<<<gPrep, TPB>>>(x, src, dst);             // launch 0: count + x->fp16
    k_scan_local<<<SCAN_BLK, 256>>>();               // launch 1 (incl. bsum scan)
    k_scatter<<<gE4, TPB>>>(src, dst, ew);           // launch 2

    // Layer 1 aggregate (fp16 gather) — launch 3 (ncu capture slot)
    k_aggregate<<<gAgg, TPB>>>(h16, agg);
    // Residual GEMM (independent; fp32 x input, fp32 out)
    k_gemm<false,false,false><<<gGemm, TG, GEMM_SMEM>>>(x, Wr, br, nullptr, res);
    k_gemm<true,false,true><<<gGemm, TG, GEMM_SMEM>>>(agg, W1, b1, nullptr, h16);

    // Layers 2-3
    k_aggregate<<<gAgg, TPB>>>(h16, agg);
    k_gemm<true,false,true><<<gGemm, TG, GEMM_SMEM>>>(agg, W2, b2, nullptr, h16);
    k_aggregate<<<gAgg, TPB>>>(h16, agg);
    k_gemm<true,false,true><<<gGemm, TG, GEMM_SMEM>>>(agg, W3, b3, nullptr, h16);

    // Layer 4: aggregate, gemm with fused residual+relu (fp32 out), projection
    k_aggregate<<<gAgg, TPB>>>(h16, agg);
    k_gemm<true,true,false><<<gGemm, TG, GEMM_SMEM>>>(agg, W4, b4, res, hA);
    k_gemm_out<<<gGemm, TG, OUT_SMEM>>>(hA, Wo, bo, out);
}

// round 13
// speedup vs baseline: 1.6266x; 1.1791x over previous
#include <cuda_runtime.h>
#include <cuda_fp16.h>

// Problem constants (from reference setup_inputs)
#define N_NODES  100000
#define N_EDGES  1600000
#define PADN     102400           // 100 scan blocks x 1024
#define DIM      64
#define COUT     32
#define SCAN_BLK 100
#define SCAN_ELEMS 1024

#define GEMM_ROWS 128             // rows per block tile
#define AST_STRIDE 132            // padded row stride of transposed A (floats)
#define GEMM_SMEM ((64 * AST_STRIDE + 64 * 64) * 4)   // 50176 B
#define OUT_SMEM  ((64 * AST_STRIDE + 64 * 32) * 4)   // 41984 B

typedef unsigned long long u64;

// ---- packed f32x2 helpers (sm_103a FFMA2) ----------------------------------
__device__ __forceinline__ u64 f32x2_dup(float a) {
    u64 r;
    asm("mov.b64 %0, {%1, %1};" : "=l"(r) : "f"(a));
    return r;
}
__device__ __forceinline__ void f32x2_fma(u64& d, u64 a, u64 b) {
    asm("fma.rn.f32x2 %0, %1, %2, %0;" : "+l"(d) : "l"(a), "l"(b));
}
__device__ __forceinline__ float2 f32x2_unpack(u64 v) {
    float lo, hi;
    asm("mov.b64 {%0, %1}, %2;" : "=f"(lo), "=f"(hi) : "l"(v));
    return make_float2(lo, hi);
}
__device__ __forceinline__ unsigned h2bits(__half2 h) {
    return *(unsigned*)&h;
}

// ---------------------------------------------------------------------------
// Static device scratch (no cudaMalloc allowed)
// ---------------------------------------------------------------------------
__device__ int    g_deg_out[PADN];
__device__ int    g_deg_in[PADN];
__device__ int    g_sync;              // last-block-done counter (zeroed per call)
__device__ float  g_norm_s[N_NODES];
__device__ float  g_norm_d[N_NODES];
__device__ int    g_off[N_NODES + 1];  // local (per-scan-block) exclusive prefix
__device__ int    g_cursor[N_NODES];
__device__ int    g_bsum[SCAN_BLK];
__device__ int    g_boff[SCAN_BLK];    // exclusive prefix of block sums
__device__ __align__(16) int2 g_edges[N_EDGES];  // (src byte-offset(fp16 row), w)
__device__ float  g_agg[N_NODES * DIM];
__device__ float  g_hA[N_NODES * DIM];
__device__ float  g_res[N_NODES * DIM];
__device__ __align__(16) __half g_h16[N_NODES * DIM];  // fp16 gather source

// ---------------------------------------------------------------------------
// Prologue: degree count (4 edges/thread) + x -> fp16 conversion (8 elems/thr)
// ---------------------------------------------------------------------------
__global__ void __launch_bounds__(256) k_prep(const float* __restrict__ x,
                                              const int* __restrict__ src,
                                              const int* __restrict__ dst) {
    int t = blockIdx.x * blockDim.x + threadIdx.x;
    if (t < N_NODES * DIM / 8) {
        float4 a = ((const float4*)x)[2 * t];
        float4 b = ((const float4*)x)[2 * t + 1];
        uint4 u;
        u.x = h2bits(__floats2half2_rn(a.x, a.y));
        u.y = h2bits(__floats2half2_rn(a.z, a.w));
        u.z = h2bits(__floats2half2_rn(b.x, b.y));
        u.w = h2bits(__floats2half2_rn(b.z, b.w));
        ((uint4*)g_h16)[t] = u;
    }
    if (t < N_EDGES / 4) {
        int4 s = ((const int4*)src)[t];
        int4 d = ((const int4*)dst)[t];
        atomicAdd(&g_deg_out[s.x], 1); atomicAdd(&g_deg_out[s.y], 1);
        atomicAdd(&g_deg_out[s.z], 1); atomicAdd(&g_deg_out[s.w], 1);
        atomicAdd(&g_deg_in[d.x], 1);  atomicAdd(&g_deg_in[d.y], 1);
        atomicAdd(&g_deg_in[d.z], 1);  atomicAdd(&g_deg_in[d.w], 1);
    }
}

// Per-block local exclusive scan of deg_in + norms; LAST block scans block sums.
__global__ void __launch_bounds__(256) k_scan_local() {
    __shared__ int wexcl[8];
    __shared__ int s_last;
    const int tid  = threadIdx.x;
    const int lane = tid & 31;
    const int wid  = tid >> 5;
    const int i0   = blockIdx.x * SCAN_ELEMS + tid * 4;

    int4 v = *((const int4*)(g_deg_in + i0));

    if (i0 < N_NODES) {   // N_NODES % 4 == 0
        int4 o = *((const int4*)(g_deg_out + i0));
        g_norm_d[i0 + 0] = rsqrtf((float)max(v.x, 1));
        g_norm_d[i0 + 1] = rsqrtf((float)max(v.y, 1));
        g_norm_d[i0 + 2] = rsqrtf((float)max(v.z, 1));
        g_norm_d[i0 + 3] = rsqrtf((float)max(v.w, 1));
        g_norm_s[i0 + 0] = rsqrtf((float)max(o.x, 1));
        g_norm_s[i0 + 1] = rsqrtf((float)max(o.y, 1));
        g_norm_s[i0 + 2] = rsqrtf((float)max(o.z, 1));
        g_norm_s[i0 + 3] = rsqrtf((float)max(o.w, 1));
    }

    int sum = v.x + v.y + v.z + v.w;
    int x = sum;
    #pragma unroll
    for (int o = 1; o < 32; o <<= 1) {
        int t = __shfl_up_sync(0xffffffffu, x, o);
        if (lane >= o) x += t;
    }
    if (lane == 31) wexcl[wid] = x;
    __syncthreads();
    if (wid == 0 && lane < 8) {
        int t = wexcl[lane];
        int y = t;
        #pragma unroll
        for (int o = 1; o < 8; o <<= 1) {
            int u = __shfl_up_sync(0xffu, y, o);
            if (lane >= o) y += u;
        }
        wexcl[lane] = y - t;
    }
    __syncthreads();

    int excl = (x - sum) + wexcl[wid];
    if (i0 < N_NODES) {
        int4 w;
        w.x = excl;
        w.y = excl + v.x;
        w.z = excl + v.x + v.y;
        w.w = excl + v.x + v.y + v.z;
        *((int4*)(g_off + i0))    = w;
        *((int4*)(g_cursor + i0)) = w;
    }
    if (tid == 255) g_bsum[blockIdx.x] = excl + sum;

    // ---- last finished block scans the 100 block sums -> g_boff ----
    __threadfence();
    if (tid == 0) s_last = (atomicAdd(&g_sync, 1) == SCAN_BLK - 1);
    __syncthreads();
    if (s_last && tid < 128) {
        __shared__ int wtot[4];
        int val = (tid < SCAN_BLK) ? g_bsum[tid] : 0;
        int xx = val;
        #pragma unroll
        for (int o = 1; o < 32; o <<= 1) {
            int t = __shfl_up_sync(0xffffffffu, xx, o);
            if (lane >= o) xx += t;
        }
        if (lane == 31) wtot[wid] = xx;
        __syncwarp();
        __syncthreads();
        int woff = 0;
        #pragma unroll
        for (int w = 0; w < 4; w++) if (w < wid) woff += wtot[w];
        if (tid < SCAN_BLK) g_boff[tid] = woff + xx - val;
    }
}

// Counting-sort scatter (4 edges/thread): pack (src byte-offset in fp16 rows
// = src*128, ew*norm_s[src]) grouped by dst.
__global__ void __launch_bounds__(256) k_scatter(const int* __restrict__ src,
                                                 const int* __restrict__ dst,
                                                 const float* __restrict__ ew) {
    int t = blockIdx.x * blockDim.x + threadIdx.x;
    if (t < N_EDGES / 4) {
        int4   s = ((const int4*)src)[t];
        int4   d = ((const int4*)dst)[t];
        float4 w = ((const float4*)ew)[t];
        int p;
        p = atomicAdd(&g_cursor[d.x], 1) + g_boff[d.x >> 10];
        g_edges[p] = make_int2(s.x << 7, __float_as_int(w.x * g_norm_s[s.x]));
        p = atomicAdd(&g_cursor[d.y], 1) + g_boff[d.y >> 10];
        g_edges[p] = make_int2(s.y << 7, __float_as_int(w.y * g_norm_s[s.y]));
        p = atomicAdd(&g_cursor[d.z], 1) + g_boff[d.z >> 10];
        g_edges[p] = make_int2(s.z << 7, __float_as_int(w.z * g_norm_s[s.z]));
        p = atomicAdd(&g_cursor[d.w], 1) + g_boff[d.w >> 10];
        g_edges[p] = make_int2(s.w << 7, __float_as_int(w.w * g_norm_s[s.w]));
    }
}

// ---------------------------------------------------------------------------
// Aggregation: one warp per dst node, QUARTER-warp per edge.
// 8 lanes x uint4(16B) = one LDG.128 gathers a full fp16 row; each gather
// instruction serves 4 edges (one per quarter). 8 edges in flight per warp.
// fp32 accumulate; cross-quarter shfl_xor reduction.
// ---------------------------------------------------------------------------
__global__ void __launch_bounds__(256) k_aggregate(const __half* __restrict__ in,
                                                   float* __restrict__ outagg) {
    int gw = (blockIdx.x * blockDim.x + threadIdx.x) >> 5;
    if (gw >= N_NODES) return;
    const int lane = threadIdx.x & 31;
    const int q    = lane >> 3;          // quarter 0..3
    const int l8   = lane & 7;           // lane within quarter -> cols l8*8..+7

    const int beg = g_off[gw] + g_boff[gw >> 10];
    const int end = (gw + 1 == N_NODES) ? N_EDGES
                                        : g_off[gw + 1] + g_boff[(gw + 1) >> 10];

    float* orow = outagg + (size_t)gw * DIM + l8 * 8;

    if (beg >= end) {   // degree-0: agg = 0
        if (lane < 8) {
            float4 z = make_float4(0.f, 0.f, 0.f, 0.f);
            *((float4*)orow)       = z;
            *((float4*)(orow + 4)) = z;
        }
        return;
    }

    const char* base = (const char*)in + l8 * 16;   // 8 half cols per lane
    float acc[8];
    #pragma unroll
    for (int j = 0; j < 8; j++) acc[j] = 0.f;

    for (int e = beg; e < end; e += 8) {
        // quarter q handles edges e+q and e+4+q (clamped, zero-weighted)
        int i0 = min(e + q,     end - 1);
        int i1 = min(e + 4 + q, end - 1);
        int2 m0 = g_edges[i0];
        int2 m1 = g_edges[i1];
        float w0 = (e + q     < end) ? __int_as_float(m0.y) : 0.f;
        float w1 = (e + 4 + q < end) ? __int_as_float(m1.y) : 0.f;
        uint4 x0 = *((const uint4*)(base + m0.x));
        uint4 x1 = *((const uint4*)(base + m1.x));

        const __half2* h0 = (const __half2*)&x0;
        const __half2* h1 = (const __half2*)&x1;
        #pragma unroll
        for (int p = 0; p < 4; p++) {
            float2 f0 = __half22float2(h0[p]);
            float2 f1 = __half22float2(h1[p]);
            acc[2 * p]     += f0.x * w0;
            acc[2 * p + 1] += f0.y * w0;
            acc[2 * p]     += f1.x * w1;
            acc[2 * p + 1] += f1.y * w1;
        }
    }

    // cross-quarter reduction (same column mapping in every quarter)
    #pragma unroll
    for (int j = 0; j < 8; j++) {
        acc[j] += __shfl_xor_sync(0xffffffffu, acc[j], 8);
        acc[j] += __shfl_xor_sync(0xffffffffu, acc[j], 16);
    }

    if (lane < 8) {
        float nd = g_norm_d[gw];
        float4 o0, o1;
        o0.x = acc[0] * nd; o0.y = acc[1] * nd;
        o0.z = acc[2] * nd; o0.w = acc[3] * nd;
        o1.x = acc[4] * nd; o1.y = acc[5] * nd;
        o1.z = acc[6] * nd; o1.w = acc[7] * nd;
        *((float4*)orow)       = o0;
        *((float4*)(orow + 4)) = o1;
    }
}

// ---------------------------------------------------------------------------
// Register-blocked SGEMM, outer product + packed FFMA2.
// Tile 128 rows x 64 cols, 128 threads, each thread 8 rows x 8 cols.
// HALFOUT: write fp16 (for the next layer's gather); else fp32.
// ---------------------------------------------------------------------------
template <bool RELU, bool ADDRES, bool HALFOUT>
__global__ void __launch_bounds__(128, 4) k_gemm(const float* __restrict__ in,
                                                 const float* __restrict__ W,
                                                 const float* __restrict__ b,
                                                 const float* __restrict__ res,
                                                 void* __restrict__ outv) {
    extern __shared__ float smem[];
    float* AsT = smem;                       // [64][AST_STRIDE]  (A transposed)
    float* Ws  = smem + 64 * AST_STRIDE;     // [64][64]

    const int tid  = threadIdx.x;            // 128 threads
    const int row0 = blockIdx.x * GEMM_ROWS;

    {
        const int r  = tid;
        const int gr = row0 + r;
        if (gr < N_NODES) {
            const float4* ap = (const float4*)(in + (size_t)gr * DIM);
            #pragma unroll
            for (int c4 = 0; c4 < 16; c4++) {
                float4 v = ap[c4];
                AsT[(c4 * 4 + 0) * AST_STRIDE + r] = v.x;
                AsT[(c4 * 4 + 1) * AST_STRIDE + r] = v.y;
                AsT[(c4 * 4 + 2) * AST_STRIDE + r] = v.z;
                AsT[(c4 * 4 + 3) * AST_STRIDE + r] = v.w;
            }
        } else {
            #pragma unroll
            for (int c = 0; c < 64; c++)
                AsT[c * AST_STRIDE + r] = 0.f;
        }
    }
    #pragma unroll
    for (int i = tid; i < 64 * 16; i += 128)
        ((float4*)Ws)[i] = ((const float4*)W)[i];
    __syncthreads();

    const int tx = tid & 7;                  // col group: cols tx*8 .. +7
    const int ty = tid >> 3;                 // row group: rows ty*8 .. +7

    u64 acc[4][8];                           // [row-pair][col]
    #pragma unroll
    for (int i = 0; i < 4; i++)
        #pragma unroll
        for (int j = 0; j < 8; j++) acc[i][j] = 0ull;

    #pragma unroll
    for (int k = 0; k < 64; k++) {
        ulonglong2 A0 = *((const ulonglong2*)&AsT[k * AST_STRIDE + ty * 8]);
        ulonglong2 A1 = *((const ulonglong2*)&AsT[k * AST_STRIDE + ty * 8 + 4]);
        u64 ap[4] = {A0.x, A0.y, A1.x, A1.y};
        float4 B0 = *((const float4*)&Ws[k * 64 + tx * 8]);
        float4 B1 = *((const float4*)&Ws[k * 64 + tx * 8 + 4]);
        u64 bd[8];
        bd[0] = f32x2_dup(B0.x); bd[1] = f32x2_dup(B0.y);
        bd[2] = f32x2_dup(B0.z); bd[3] = f32x2_dup(B0.w);
        bd[4] = f32x2_dup(B1.x); bd[5] = f32x2_dup(B1.y);
        bd[6] = f32x2_dup(B1.z); bd[7] = f32x2_dup(B1.w);
        #pragma unroll
        for (int i = 0; i < 4; i++)
            #pragma unroll
            for (int j = 0; j < 8; j++)
                f32x2_fma(acc[i][j], ap[i], bd[j]);
    }

    float4 bv0 = *((const float4*)(b + tx * 8));
    float4 bv1 = *((const float4*)(b + tx * 8 + 4));
    #pragma unroll
    for (int i2 = 0; i2 < 4; i2++) {
        float2 c0 = f32x2_unpack(acc[i2][0]);
        float2 c1 = f32x2_unpack(acc[i2][1]);
        float2 c2 = f32x2_unpack(acc[i2][2]);
        float2 c3 = f32x2_unpack(acc[i2][3]);
        float2 c4 = f32x2_unpack(acc[i2][4]);
        float2 c5 = f32x2_unpack(acc[i2][5]);
        float2 c6 = f32x2_unpack(acc[i2][6]);
        float2 c7 = f32x2_unpack(acc[i2][7]);
        #pragma unroll
        for (int h = 0; h < 2; h++) {
            int gr = row0 + ty * 8 + i2 * 2 + h;
            if (gr < N_NODES) {
                float4 o0, o1;
                o0.x = (h ? c0.y : c0.x) + bv0.x;
                o0.y = (h ? c1.y : c1.x) + bv0.y;
                o0.z = (h ? c2.y : c2.x) + bv0.z;
                o0.w = (h ? c3.y : c3.x) + bv0.w;
                o1.x = (h ? c4.y : c4.x) + bv1.x;
                o1.y = (h ? c5.y : c5.x) + bv1.y;
                o1.z = (h ? c6.y : c6.x) + bv1.z;
                o1.w = (h ? c7.y : c7.x) + bv1.w;
                if (ADDRES) {
                    const float* rr = res + (size_t)gr * DIM + tx * 8;
                    float4 r0 = *((const float4*)rr);
                    float4 r1 = *((const float4*)(rr + 4));
                    o0.x += r0.x; o0.y += r0.y; o0.z += r0.z; o0.w += r0.w;
                    o1.x += r1.x; o1.y += r1.y; o1.z += r1.z; o1.w += r1.w;
                }
                if (RELU) {
                    o0.x = fmaxf(o0.x, 0.f); o0.y = fmaxf(o0.y, 0.f);
                    o0.z = fmaxf(o0.z, 0.f); o0.w = fmaxf(o0.w, 0.f);
                    o1.x = fmaxf(o1.x, 0.f); o1.y = fmaxf(o1.y, 0.f);
                    o1.z = fmaxf(o1.z, 0.f); o1.w = fmaxf(o1.w, 0.f);
                }
                if (HALFOUT) {
                    uint4 u;
                    u.x = h2bits(__floats2half2_rn(o0.x, o0.y));
                    u.y = h2bits(__floats2half2_rn(o0.z, o0.w));
                    u.z = h2bits(__floats2half2_rn(o1.x, o1.y));
                    u.w = h2bits(__floats2half2_rn(o1.z, o1.w));
                    *((uint4*)((__half*)outv + (size_t)gr * DIM + tx * 8)) = u;
                } else {
                    float* op = (float*)outv + (size_t)gr * DIM + tx * 8;
                    *((float4*)op)       = o0;
                    *((float4*)(op + 4)) = o1;
                }
            }
        }
    }
}

// ---------------------------------------------------------------------------
// Output projection: out[N,32] = in[N,64] @ Wo[64,32] + bo.
// ---------------------------------------------------------------------------
__global__ void __launch_bounds__(128, 4) k_gemm_out(const float* __restrict__ in,
                                                     const float* __restrict__ Wo,
                                                     const float* __restrict__ bo,
                                                     float* __restrict__ out) {
    extern __shared__ float smem[];
    float* AsT = smem;                       // [64][AST_STRIDE]
    float* Ws  = smem + 64 * AST_STRIDE;     // [64][32]

    const int tid  = threadIdx.x;
    const int row0 = blockIdx.x * GEMM_ROWS;

    {
        const int r  = tid;
        const int gr = row0 + r;
        if (gr < N_NODES) {
            const float4* ap = (const float4*)(in + (size_t)gr * DIM);
            #pragma unroll
            for (int c4 = 0; c4 < 16; c4++) {
                float4 v = ap[c4];
                AsT[(c4 * 4 + 0) * AST_STRIDE + r] = v.x;
                AsT[(c4 * 4 + 1) * AST_STRIDE + r] = v.y;
                AsT[(c4 * 4 + 2) * AST_STRIDE + r] = v.z;
                AsT[(c4 * 4 + 3) * AST_STRIDE + r] = v.w;
            }
        } else {
            #pragma unroll
            for (int c = 0; c < 64; c++)
                AsT[c * AST_STRIDE + r] = 0.f;
        }
    }
    #pragma unroll
    for (int i = tid; i < 64 * 8; i += 128)
        ((float4*)Ws)[i] = ((const float4*)Wo)[i];
    __syncthreads();

    const int tx = tid & 7;                  // col group: cols tx*4 .. +3
    const int ty = tid >> 3;                 // row group: rows ty*8 .. +7

    u64 acc[4][4];                           // [row-pair][col]
    #pragma unroll
    for (int i = 0; i < 4; i++)
        #pragma unroll
        for (int j = 0; j < 4; j++) acc[i][j] = 0ull;

    #pragma unroll
    for (int k = 0; k < 64; k++) {
        ulonglong2 A0 = *((const ulonglong2*)&AsT[k * AST_STRIDE + ty * 8]);
        ulonglong2 A1 = *((const ulonglong2*)&AsT[k * AST_STRIDE + ty * 8 + 4]);
        u64 ap[4] = {A0.x, A0.y, A1.x, A1.y};
        float4 B0 = *((const float4*)&Ws[k * 32 + tx * 4]);
        u64 bd[4];
        bd[0] = f32x2_dup(B0.x); bd[1] = f32x2_dup(B0.y);
        bd[2] = f32x2_dup(B0.z); bd[3] = f32x2_dup(B0.w);
        #pragma unroll
        for (int i = 0; i < 4; i++)
            #pragma unroll
            for (int j = 0; j < 4; j++)
                f32x2_fma(acc[i][j], ap[i], bd[j]);
    }

    float4 bv = *((const float4*)(bo + tx * 4));
    #pragma unroll
    for (int i2 = 0; i2 < 4; i2++) {
        float2 c0 = f32x2_unpack(acc[i2][0]);
        float2 c1 = f32x2_unpack(acc[i2][1]);
        float2 c2 = f32x2_unpack(acc[i2][2]);
        float2 c3 = f32x2_unpack(acc[i2][3]);
        #pragma unroll
        for (int h = 0; h < 2; h++) {
            int gr = row0 + ty * 8 + i2 * 2 + h;
            if (gr < N_NODES) {
                float4 o;
                o.x = (h ? c0.y : c0.x) + bv.x;
                o.y = (h ? c1.y : c1.x) + bv.y;
                o.z = (h ? c2.y : c2.x) + bv.z;
                o.w = (h ? c3.y : c3.x) + bv.w;
                *((float4*)(out + (size_t)gr * COUT + tx * 4)) = o;
            }
        }
    }
}

// ---------------------------------------------------------------------------
// Launch
// ---------------------------------------------------------------------------
extern "C" void kernel_launch(void* const* d_in, const int* in_sizes, int n_in,
                              void* d_out, int out_size) {
    const float* x   = (const float*)d_in[0];
    const int*   src = (const int*)d_in[1];
    const int*   dst = (const int*)d_in[2];
    const float* ew  = (const float*)d_in[3];
    const float* W1 = (const float*)d_in[4];
    const float* b1 = (const float*)d_in[5];
    const float* W2 = (const float*)d_in[6];
    const float* b2 = (const float*)d_in[7];
    const float* W3 = (const float*)d_in[8];
    const float* b3 = (const float*)d_in[9];
    const float* W4 = (const float*)d_in[10];
    const float* b4 = (const float*)d_in[11];
    const float* Wr = (const float*)d_in[12];
    const float* br = (const float*)d_in[13];
    const float* Wo = (const float*)d_in[14];
    const float* bo = (const float*)d_in[15];
    float* out = (float*)d_out;

    float*  agg; cudaGetSymbolAddress((void**)&agg, g_agg);
    float*  hA;  cudaGetSymbolAddress((void**)&hA,  g_hA);
    float*  res; cudaGetSymbolAddress((void**)&res, g_res);
    __half* h16; cudaGetSymbolAddress((void**)&h16, g_h16);
    int* degout; cudaGetSymbolAddress((void**)&degout, g_deg_out);
    int* degin;  cudaGetSymbolAddress((void**)&degin,  g_deg_in);
    int* syncp;  cudaGetSymbolAddress((void**)&syncp,  g_sync);

    cudaFuncSetAttribute(k_gemm<false,false,false>, cudaFuncAttributeMaxDynamicSharedMemorySize, GEMM_SMEM);
    cudaFuncSetAttribute(k_gemm<true,false,true>,   cudaFuncAttributeMaxDynamicSharedMemorySize, GEMM_SMEM);
    cudaFuncSetAttribute(k_gemm<true,true,false>,   cudaFuncAttributeMaxDynamicSharedMemorySize, GEMM_SMEM);
    cudaFuncSetAttribute(k_gemm_out,                cudaFuncAttributeMaxDynamicSharedMemorySize, OUT_SMEM);

    const int TPB = 256;
    const int gE4  = (N_EDGES / 4 + TPB - 1) / TPB;
    const int gPrep = (N_NODES * DIM / 8 + TPB - 1) / TPB;       // 3125 (>= gE4)
    const int gAgg  = (N_NODES * 32 + TPB - 1) / TPB;            // warp per node
    const int gGemm = (N_NODES + GEMM_ROWS - 1) / GEMM_ROWS;     // 782
    const int TG = 128;

    cudaMemsetAsync(degout, 0, PADN * sizeof(int));
    cudaMemsetAsync(degin,  0, PADN * sizeof(int));
    cudaMemsetAsync(syncp,  0, sizeof(int));

    k_prep<<<gPrep, TPB>>>(x, src, dst);             // launch 0: count + x->fp16
    k_scan_local<<<SCAN_BLK, 256>>>();               // launch 1 (incl. bsum scan)
    k_scatter<<<gE4, TPB>>>(src, dst, ew);           // launch 2

    // Layer 1 aggregate (fp16 quarter-warp gather) — launch 3 (ncu capture slot)
    k_aggregate<<<gAgg, TPB>>>(h16, agg);
    // Residual GEMM (independent; fp32 x input, fp32 out)
    k_gemm<false,false,false><<<gGemm, TG, GEMM_SMEM>>>(x, Wr, br, nullptr, res);
    k_gemm<true,false,true><<<gGemm, TG, GEMM_SMEM>>>(agg, W1, b1, nullptr, h16);

    // Layers 2-3
    k_aggregate<<<gAgg, TPB>>>(h16, agg);
    k_gemm<true,false,true><<<gGemm, TG, GEMM_SMEM>>>(agg, W2, b2, nullptr, h16);
    k_aggregate<<<gAgg, TPB>>>(h16, agg);
    k_gemm<true,false,true><<<gGemm, TG, GEMM_SMEM>>>(agg, W3, b3, nullptr, h16);

    // Layer 4: aggregate, gemm with fused residual+relu (fp32 out), projection
    k_aggregate<<<gAgg, TPB>>>(h16, agg);
    k_gemm<true,true,false><<<gGemm, TG, GEMM_SMEM>>>(agg, W4, b4, res, hA);
    k_gemm_out<<<gGemm, TG, OUT_SMEM>>>(hA, Wo, bo, out);
}

// round 14
// speedup vs baseline: 2.2254x; 1.3681x over previous
#include <cuda_runtime.h>
#include <cuda_fp16.h>

// Problem constants (from reference setup_inputs)
#define N_NODES  100000
#define N_EDGES  1600000
#define PADN     102400           // 100 scan blocks x 1024
#define DIM      64
#define COUT     32
#define SCAN_BLK 100
#define SCAN_ELEMS 1024

#define GEMM_ROWS 128
#define AST_STRIDE 132            // fp32 transposed-A stride (gemm_out only)
#define OUT_SMEM  ((64 * AST_STRIDE + 64 * 32) * 4)   // 41984 B

typedef unsigned long long u64;

// ---- packed f32x2 helpers (sm_103a FFMA2, used by k_gemm_out) ---------------
__device__ __forceinline__ u64 f32x2_dup(float a) {
    u64 r;
    asm("mov.b64 %0, {%1, %1};" : "=l"(r) : "f"(a));
    return r;
}
__device__ __forceinline__ void f32x2_fma(u64& d, u64 a, u64 b) {
    asm("fma.rn.f32x2 %0, %1, %2, %0;" : "+l"(d) : "l"(a), "l"(b));
}
__device__ __forceinline__ float2 f32x2_unpack(u64 v) {
    float lo, hi;
    asm("mov.b64 {%0, %1}, %2;" : "=f"(lo), "=f"(hi) : "l"(v));
    return make_float2(lo, hi);
}
__device__ __forceinline__ unsigned h2bits(__half2 h) {
    return *(unsigned*)&h;
}
__device__ __forceinline__ unsigned smem_u32(const void* p) {
    return (unsigned)__cvta_generic_to_shared(p);
}

// ---------------------------------------------------------------------------
// Static device scratch (no cudaMalloc allowed)
// ---------------------------------------------------------------------------
__device__ int    g_deg_out[PADN];
__device__ int    g_deg_in[PADN];
__device__ int    g_sync;
__device__ float  g_norm_s[N_NODES];
__device__ float  g_norm_d[N_NODES];
__device__ int    g_off[N_NODES + 1];
__device__ int    g_cursor[N_NODES];
__device__ int    g_bsum[SCAN_BLK];
__device__ int    g_boff[SCAN_BLK];
__device__ __align__(16) int2 g_edges[N_EDGES];      // (src byte-offset, weight)
__device__ float  g_hA[N_NODES * DIM];               // fp32 layer-4 output
__device__ float  g_res[N_NODES * DIM];              // fp32 residual
__device__ __align__(16) __half g_x16[N_NODES * DIM];   // fp16 x (gather L1 + res gemm)
__device__ __align__(16) __half g_h16[N_NODES * DIM];   // fp16 layer outputs (gather)
__device__ __align__(16) __half g_agg16[N_NODES * DIM]; // fp16 aggregate (gemm A)
__device__ __align__(16) __half g_W16[5 * DIM * DIM];   // fp16 W1,W2,W3,W4,Wr

// ---------------------------------------------------------------------------
// Prologue: degree count + x->fp16 + weights->fp16
// ---------------------------------------------------------------------------
__global__ void __launch_bounds__(256) k_prep(const float* __restrict__ x,
                                              const int* __restrict__ src,
                                              const int* __restrict__ dst,
                                              const float* __restrict__ W1,
                                              const float* __restrict__ W2,
                                              const float* __restrict__ W3,
                                              const float* __restrict__ W4,
                                              const float* __restrict__ Wr) {
    int t = blockIdx.x * blockDim.x + threadIdx.x;
    if (t < N_NODES * DIM / 8) {
        float4 a = ((const float4*)x)[2 * t];
        float4 b = ((const float4*)x)[2 * t + 1];
        uint4 u;
        u.x = h2bits(__floats2half2_rn(a.x, a.y));
        u.y = h2bits(__floats2half2_rn(a.z, a.w));
        u.z = h2bits(__floats2half2_rn(b.x, b.y));
        u.w = h2bits(__floats2half2_rn(b.z, b.w));
        ((uint4*)g_x16)[t] = u;
    }
    if (t < N_EDGES / 4) {
        int4 s = ((const int4*)src)[t];
        int4 d = ((const int4*)dst)[t];
        atomicAdd(&g_deg_out[s.x], 1); atomicAdd(&g_deg_out[s.y], 1);
        atomicAdd(&g_deg_out[s.z], 1); atomicAdd(&g_deg_out[s.w], 1);
        atomicAdd(&g_deg_in[d.x], 1);  atomicAdd(&g_deg_in[d.y], 1);
        atomicAdd(&g_deg_in[d.z], 1);  atomicAdd(&g_deg_in[d.w], 1);
    }
    if (t < 5 * 512) {                       // 5 matrices x 4096 elems / 8
        int m = t >> 9;
        int i = t & 511;
        const float* Wsrc = (m == 0) ? W1 : (m == 1) ? W2 : (m == 2) ? W3
                           : (m == 3) ? W4 : Wr;
        float4 a = ((const float4*)Wsrc)[2 * i];
        float4 b = ((const float4*)Wsrc)[2 * i + 1];
        uint4 u;
        u.x = h2bits(__floats2half2_rn(a.x, a.y));
        u.y = h2bits(__floats2half2_rn(a.z, a.w));
        u.z = h2bits(__floats2half2_rn(b.x, b.y));
        u.w = h2bits(__floats2half2_rn(b.z, b.w));
        ((uint4*)(g_W16 + m * DIM * DIM))[i] = u;
    }
}

// Per-block local exclusive scan of deg_in + norms; LAST block scans block sums.
__global__ void __launch_bounds__(256) k_scan_local() {
    __shared__ int wexcl[8];
    __shared__ int s_last;
    const int tid  = threadIdx.x;
    const int lane = tid & 31;
    const int wid  = tid >> 5;
    const int i0   = blockIdx.x * SCAN_ELEMS + tid * 4;

    int4 v = *((const int4*)(g_deg_in + i0));

    if (i0 < N_NODES) {   // N_NODES % 4 == 0
        int4 o = *((const int4*)(g_deg_out + i0));
        g_norm_d[i0 + 0] = rsqrtf((float)max(v.x, 1));
        g_norm_d[i0 + 1] = rsqrtf((float)max(v.y, 1));
        g_norm_d[i0 + 2] = rsqrtf((float)max(v.z, 1));
        g_norm_d[i0 + 3] = rsqrtf((float)max(v.w, 1));
        g_norm_s[i0 + 0] = rsqrtf((float)max(o.x, 1));
        g_norm_s[i0 + 1] = rsqrtf((float)max(o.y, 1));
        g_norm_s[i0 + 2] = rsqrtf((float)max(o.z, 1));
        g_norm_s[i0 + 3] = rsqrtf((float)max(o.w, 1));
    }

    int sum = v.x + v.y + v.z + v.w;
    int x = sum;
    #pragma unroll
    for (int o = 1; o < 32; o <<= 1) {
        int t = __shfl_up_sync(0xffffffffu, x, o);
        if (lane >= o) x += t;
    }
    if (lane == 31) wexcl[wid] = x;
    __syncthreads();
    if (wid == 0 && lane < 8) {
        int t = wexcl[lane];
        int y = t;
        #pragma unroll
        for (int o = 1; o < 8; o <<= 1) {
            int u = __shfl_up_sync(0xffu, y, o);
            if (lane >= o) y += u;
        }
        wexcl[lane] = y - t;
    }
    __syncthreads();

    int excl = (x - sum) + wexcl[wid];
    if (i0 < N_NODES) {
        int4 w;
        w.x = excl;
        w.y = excl + v.x;
        w.z = excl + v.x + v.y;
        w.w = excl + v.x + v.y + v.z;
        *((int4*)(g_off + i0))    = w;
        *((int4*)(g_cursor + i0)) = w;
    }
    if (tid == 255) g_bsum[blockIdx.x] = excl + sum;

    __threadfence();
    if (tid == 0) s_last = (atomicAdd(&g_sync, 1) == SCAN_BLK - 1);
    __syncthreads();
    if (s_last && tid < 128) {
        __shared__ int wtot[4];
        int val = (tid < SCAN_BLK) ? g_bsum[tid] : 0;
        int xx = val;
        #pragma unroll
        for (int o = 1; o < 32; o <<= 1) {
            int t = __shfl_up_sync(0xffffffffu, xx, o);
            if (lane >= o) xx += t;
        }
        if (lane == 31) wtot[wid] = xx;
        __syncwarp();
        __syncthreads();
        int woff = 0;
        #pragma unroll
        for (int w = 0; w < 4; w++) if (w < wid) woff += wtot[w];
        if (tid < SCAN_BLK) g_boff[tid] = woff + xx - val;
    }
}

// Counting-sort scatter (4 edges/thread)
__global__ void __launch_bounds__(256) k_scatter(const int* __restrict__ src,
                                                 const int* __restrict__ dst,
                                                 const float* __restrict__ ew) {
    int t = blockIdx.x * blockDim.x + threadIdx.x;
    if (t < N_EDGES / 4) {
        int4   s = ((const int4*)src)[t];
        int4   d = ((const int4*)dst)[t];
        float4 w = ((const float4*)ew)[t];
        int p;
        p = atomicAdd(&g_cursor[d.x], 1) + g_boff[d.x >> 10];
        g_edges[p] = make_int2(s.x << 7, __float_as_int(w.x * g_norm_s[s.x]));
        p = atomicAdd(&g_cursor[d.y], 1) + g_boff[d.y >> 10];
        g_edges[p] = make_int2(s.y << 7, __float_as_int(w.y * g_norm_s[s.y]));
        p = atomicAdd(&g_cursor[d.z], 1) + g_boff[d.z >> 10];
        g_edges[p] = make_int2(s.z << 7, __float_as_int(w.z * g_norm_s[s.z]));
        p = atomicAdd(&g_cursor[d.w], 1) + g_boff[d.w >> 10];
        g_edges[p] = make_int2(s.w << 7, __float_as_int(w.w * g_norm_s[s.w]));
    }
}

// ---------------------------------------------------------------------------
// Aggregation: one warp per dst node, QUARTER-warp per edge (fp16 rows,
// 8 lanes x 16B = one LDG.128 per row). fp32 accumulate, fp16 output.
// ---------------------------------------------------------------------------
__global__ void __launch_bounds__(256) k_aggregate(const __half* __restrict__ in,
                                                   __half* __restrict__ outagg) {
    int gw = (blockIdx.x * blockDim.x + threadIdx.x) >> 5;
    if (gw >= N_NODES) return;
    const int lane = threadIdx.x & 31;
    const int q    = lane >> 3;
    const int l8   = lane & 7;

    const int beg = g_off[gw] + g_boff[gw >> 10];
    const int end = (gw + 1 == N_NODES) ? N_EDGES
                                        : g_off[gw + 1] + g_boff[(gw + 1) >> 10];

    __half* orow = outagg + (size_t)gw * DIM + l8 * 8;

    if (beg >= end) {
        if (lane < 8) *((uint4*)orow) = make_uint4(0u, 0u, 0u, 0u);
        return;
    }

    const char* base = (const char*)in + l8 * 16;
    float acc[8];
    #pragma unroll
    for (int j = 0; j < 8; j++) acc[j] = 0.f;

    for (int e = beg; e < end; e += 8) {
        int i0 = min(e + q,     end - 1);
        int i1 = min(e + 4 + q, end - 1);
        int2 m0 = g_edges[i0];
        int2 m1 = g_edges[i1];
        float w0 = (e + q     < end) ? __int_as_float(m0.y) : 0.f;
        float w1 = (e + 4 + q < end) ? __int_as_float(m1.y) : 0.f;
        uint4 x0 = *((const uint4*)(base + m0.x));
        uint4 x1 = *((const uint4*)(base + m1.x));

        const __half2* h0 = (const __half2*)&x0;
        const __half2* h1 = (const __half2*)&x1;
        #pragma unroll
        for (int p = 0; p < 4; p++) {
            float2 f0 = __half22float2(h0[p]);
            float2 f1 = __half22float2(h1[p]);
            acc[2 * p]     += f0.x * w0;
            acc[2 * p + 1] += f0.y * w0;
            acc[2 * p]     += f1.x * w1;
            acc[2 * p + 1] += f1.y * w1;
        }
    }

    #pragma unroll
    for (int j = 0; j < 8; j++) {
        acc[j] += __shfl_xor_sync(0xffffffffu, acc[j], 8);
        acc[j] += __shfl_xor_sync(0xffffffffu, acc[j], 16);
    }

    if (lane < 8) {
        float nd = g_norm_d[gw];
        uint4 u;
        u.x = h2bits(__floats2half2_rn(acc[0] * nd, acc[1] * nd));
        u.y = h2bits(__floats2half2_rn(acc[2] * nd, acc[3] * nd));
        u.z = h2bits(__floats2half2_rn(acc[4] * nd, acc[5] * nd));
        u.w = h2bits(__floats2half2_rn(acc[6] * nd, acc[7] * nd));
        *((uint4*)orow) = u;
    }
}

// ---------------------------------------------------------------------------
// Tensor-core GEMM (HMMA): out[N,64] = op(A[N,64]h @ W[64,64]h + b).
// 128-row tile, 8 warps, warp = 16x64 strip; mma.sync.m16n8k16 fp16->fp32.
// Smem stride 72 halfs (144B = 16 mod 128) -> conflict-free ldmatrix.
// ---------------------------------------------------------------------------
template <bool RELU, bool ADDRES, bool HALFOUT>
__global__ void __launch_bounds__(256) k_gemm_mma(const __half* __restrict__ A,
                                                  const __half* __restrict__ W,
                                                  const float* __restrict__ b,
                                                  const float* __restrict__ res,
                                                  void* __restrict__ outv) {
    __shared__ __half As[128 * 72];
    __shared__ __half Wsm[64 * 72];
    const int tid  = threadIdx.x;
    const int row0 = blockIdx.x * GEMM_ROWS;

    #pragma unroll
    for (int i = tid; i < 128 * 8; i += 256) {
        int r = i >> 3, c8 = i & 7;
        int gr = row0 + r;
        uint4 v = make_uint4(0u, 0u, 0u, 0u);
        if (gr < N_NODES) v = ((const uint4*)(A + (size_t)gr * DIM))[c8];
        *((uint4*)&As[r * 72 + c8 * 8]) = v;
    }
    #pragma unroll
    for (int i = tid; i < 64 * 8; i += 256) {
        int r = i >> 3, c8 = i & 7;
        *((uint4*)&Wsm[r * 72 + c8 * 8]) = ((const uint4*)(W + r * DIM))[c8];
    }
    __syncthreads();

    const int warp = tid >> 5;
    const int lane = tid & 31;
    const int wrow = warp * 16;

    float c[8][4];
    #pragma unroll
    for (int t = 0; t < 8; t++) { c[t][0] = c[t][1] = c[t][2] = c[t][3] = 0.f; }

    const int li   = lane & 7;
    const int arow = wrow + li + ((lane >> 3) & 1) * 8;
    const int acol = (lane >> 4) * 8;
    const int brow = li + ((lane >> 3) & 1) * 8;
    const int bn   = (lane >> 4) * 8;

    const unsigned aBase = smem_u32(&As[arow * 72 + acol]);
    const unsigned bBase = smem_u32(&Wsm[brow * 72 + bn]);

    #pragma unroll
    for (int k = 0; k < 64; k += 16) {
        unsigned a0, a1, a2, a3;
        asm volatile("ldmatrix.sync.aligned.m8n8.x4.shared.b16 {%0,%1,%2,%3}, [%4];"
            : "=r"(a0), "=r"(a1), "=r"(a2), "=r"(a3)
            : "r"(aBase + k * 2));
        #pragma unroll
        for (int p = 0; p < 4; p++) {
            unsigned b0, b1, b2, b3;
            asm volatile("ldmatrix.sync.aligned.m8n8.x4.trans.shared.b16 {%0,%1,%2,%3}, [%4];"
                : "=r"(b0), "=r"(b1), "=r"(b2), "=r"(b3)
                : "r"(bBase + (unsigned)(k * 72 + p * 16) * 2));
            asm volatile("mma.sync.aligned.m16n8k16.row.col.f32.f16.f16.f32 "
                "{%0,%1,%2,%3}, {%4,%5,%6,%7}, {%8,%9}, {%0,%1,%2,%3};"
                : "+f"(c[2*p][0]), "+f"(c[2*p][1]), "+f"(c[2*p][2]), "+f"(c[2*p][3])
                : "r"(a0), "r"(a1), "r"(a2), "r"(a3), "r"(b0), "r"(b1));
            asm volatile("mma.sync.aligned.m16n8k16.row.col.f32.f16.f16.f32 "
                "{%0,%1,%2,%3}, {%4,%5,%6,%7}, {%8,%9}, {%0,%1,%2,%3};"
                : "+f"(c[2*p+1][0]), "+f"(c[2*p+1][1]), "+f"(c[2*p+1][2]), "+f"(c[2*p+1][3])
                : "r"(a0), "r"(a1), "r"(a2), "r"(a3), "r"(b2), "r"(b3));
        }
    }

    const int g  = lane >> 2;
    const int qc = (lane & 3) * 2;
    const int r1 = row0 + wrow + g;
    const int r2 = r1 + 8;
    #pragma unroll
    for (int t = 0; t < 8; t++) {
        int ct = t * 8 + qc;
        float2 bb = *((const float2*)(b + ct));
        float v0 = c[t][0] + bb.x, v1 = c[t][1] + bb.y;
        float v2 = c[t][2] + bb.x, v3 = c[t][3] + bb.y;
        if (ADDRES) {
            if (r1 < N_NODES) {
                float2 rv = *((const float2*)(res + (size_t)r1 * DIM + ct));
                v0 += rv.x; v1 += rv.y;
            }
            if (r2 < N_NODES) {
                float2 rv = *((const float2*)(res + (size_t)r2 * DIM + ct));
                v2 += rv.x; v3 += rv.y;
            }
        }
        if (RELU) {
            v0 = fmaxf(v0, 0.f); v1 = fmaxf(v1, 0.f);
            v2 = fmaxf(v2, 0.f); v3 = fmaxf(v3, 0.f);
        }
        if (HALFOUT) {
            __half* o = (__half*)outv;
            if (r1 < N_NODES) *((__half2*)(o + (size_t)r1 * DIM + ct)) = __floats2half2_rn(v0, v1);
            if (r2 < N_NODES) *((__half2*)(o + (size_t)r2 * DIM + ct)) = __floats2half2_rn(v2, v3);
        } else {
            float* o = (float*)outv;
            if (r1 < N_NODES) *((float2*)(o + (size_t)r1 * DIM + ct)) = make_float2(v0, v1);
            if (r2 < N_NODES) *((float2*)(o + (size_t)r2 * DIM + ct)) = make_float2(v2, v3);
        }
    }
}

// ---------------------------------------------------------------------------
// Output projection (fp32 FFMA2): out[N,32] = in[N,64] @ Wo[64,32] + bo.
// ---------------------------------------------------------------------------
__global__ void __launch_bounds__(128, 4) k_gemm_out(const float* __restrict__ in,
                                                     const float* __restrict__ Wo,
                                                     const float* __restrict__ bo,
                                                     float* __restrict__ out) {
    extern __shared__ float smem[];
    float* AsT = smem;                       // [64][AST_STRIDE]
    float* Ws  = smem + 64 * AST_STRIDE;     // [64][32]

    const int tid  = threadIdx.x;
    const int row0 = blockIdx.x * GEMM_ROWS;

    {
        const int r  = tid;
        const int gr = row0 + r;
        if (gr < N_NODES) {
            const float4* ap = (const float4*)(in + (size_t)gr * DIM);
            #pragma unroll
            for (int c4 = 0; c4 < 16; c4++) {
                float4 v = ap[c4];
                AsT[(c4 * 4 + 0) * AST_STRIDE + r] = v.x;
                AsT[(c4 * 4 + 1) * AST_STRIDE + r] = v.y;
                AsT[(c4 * 4 + 2) * AST_STRIDE + r] = v.z;
                AsT[(c4 * 4 + 3) * AST_STRIDE + r] = v.w;
            }
        } else {
            #pragma unroll
            for (int c = 0; c < 64; c++)
                AsT[c * AST_STRIDE + r] = 0.f;
        }
    }
    #pragma unroll
    for (int i = tid; i < 64 * 8; i += 128)
        ((float4*)Ws)[i] = ((const float4*)Wo)[i];
    __syncthreads();

    const int tx = tid & 7;
    const int ty = tid >> 3;

    u64 acc[4][4];
    #pragma unroll
    for (int i = 0; i < 4; i++)
        #pragma unroll
        for (int j = 0; j < 4; j++) acc[i][j] = 0ull;

    #pragma unroll
    for (int k = 0; k < 64; k++) {
        ulonglong2 A0 = *((const ulonglong2*)&AsT[k * AST_STRIDE + ty * 8]);
        ulonglong2 A1 = *((const ulonglong2*)&AsT[k * AST_STRIDE + ty * 8 + 4]);
        u64 ap[4] = {A0.x, A0.y, A1.x, A1.y};
        float4 B0 = *((const float4*)&Ws[k * 32 + tx * 4]);
        u64 bd[4];
        bd[0] = f32x2_dup(B0.x); bd[1] = f32x2_dup(B0.y);
        bd[2] = f32x2_dup(B0.z); bd[3] = f32x2_dup(B0.w);
        #pragma unroll
        for (int i = 0; i < 4; i++)
            #pragma unroll
            for (int j = 0; j < 4; j++)
                f32x2_fma(acc[i][j], ap[i], bd[j]);
    }

    float4 bv = *((const float4*)(bo + tx * 4));
    #pragma unroll
    for (int i2 = 0; i2 < 4; i2++) {
        float2 c0 = f32x2_unpack(acc[i2][0]);
        float2 c1 = f32x2_unpack(acc[i2][1]);
        float2 c2 = f32x2_unpack(acc[i2][2]);
        float2 c3 = f32x2_unpack(acc[i2][3]);
        #pragma unroll
        for (int h = 0; h < 2; h++) {
            int gr = row0 + ty * 8 + i2 * 2 + h;
            if (gr < N_NODES) {
                float4 o;
                o.x = (h ? c0.y : c0.x) + bv.x;
                o.y = (h ? c1.y : c1.x) + bv.y;
                o.z = (h ? c2.y : c2.x) + bv.z;
                o.w = (h ? c3.y : c3.x) + bv.w;
                *((float4*)(out + (size_t)gr * COUT + tx * 4)) = o;
            }
        }
    }
}

// ---------------------------------------------------------------------------
// Launch
// ---------------------------------------------------------------------------
extern "C" void kernel_launch(void* const* d_in, const int* in_sizes, int n_in,
                              void* d_out, int out_size) {
    const float* x   = (const float*)d_in[0];
    const int*   src = (const int*)d_in[1];
    const int*   dst = (const int*)d_in[2];
    const float* ew  = (const float*)d_in[3];
    const float* W1 = (const float*)d_in[4];
    const float* b1 = (const float*)d_in[5];
    const float* W2 = (const float*)d_in[6];
    const float* b2 = (const float*)d_in[7];
    const float* W3 = (const float*)d_in[8];
    const float* b3 = (const float*)d_in[9];
    const float* W4 = (const float*)d_in[10];
    const float* b4 = (const float*)d_in[11];
    const float* Wr = (const float*)d_in[12];
    const float* br = (const float*)d_in[13];
    const float* Wo = (const float*)d_in[14];
    const float* bo = (const float*)d_in[15];
    float* out = (float*)d_out;

    float*  hA;   cudaGetSymbolAddress((void**)&hA,   g_hA);
    float*  res;  cudaGetSymbolAddress((void**)&res,  g_res);
    __half* x16;  cudaGetSymbolAddress((void**)&x16,  g_x16);
    __half* h16;  cudaGetSymbolAddress((void**)&h16,  g_h16);
    __half* agg16;cudaGetSymbolAddress((void**)&agg16,g_agg16);
    __half* w16;  cudaGetSymbolAddress((void**)&w16,  g_W16);
    int* degout;  cudaGetSymbolAddress((void**)&degout, g_deg_out);
    int* degin;   cudaGetSymbolAddress((void**)&degin,  g_deg_in);
    int* syncp;   cudaGetSymbolAddress((void**)&syncp,  g_sync);

    cudaFuncSetAttribute(k_gemm_out, cudaFuncAttributeMaxDynamicSharedMemorySize, OUT_SMEM);

    const __half* W1h = w16;
    const __half* W2h = w16 + 1 * DIM * DIM;
    const __half* W3h = w16 + 2 * DIM * DIM;
    const __half* W4h = w16 + 3 * DIM * DIM;
    const __half* Wrh = w16 + 4 * DIM * DIM;

    const int TPB = 256;
    const int gE4   = (N_EDGES / 4 + TPB - 1) / TPB;
    const int gPrep = (N_NODES * DIM / 8 + TPB - 1) / TPB;       // 3125
    const int gAgg  = (N_NODES * 32 + TPB - 1) / TPB;
    const int gGemm = (N_NODES + GEMM_ROWS - 1) / GEMM_ROWS;     // 782

    cudaMemsetAsync(degout, 0, PADN * sizeof(int));
    cudaMemsetAsync(degin,  0, PADN * sizeof(int));
    cudaMemsetAsync(syncp,  0, sizeof(int));

    k_prep<<<gPrep, TPB>>>(x, src, dst, W1, W2, W3, W4, Wr);   // launch 0
    k_scan_local<<<SCAN_BLK, 256>>>();                         // launch 1
    k_scatter<<<gE4, TPB>>>(src, dst, ew);                     // launch 2

    // Residual GEMM (HMMA) — launch 3 (ncu capture slot)
    k_gemm_mma<false,false,false><<<gGemm, TPB>>>(x16, Wrh, br, nullptr, res);

    // Layer 1
    k_aggregate<<<gAgg, TPB>>>(x16, agg16);
    k_gemm_mma<true,false,true><<<gGemm, TPB>>>(agg16, W1h, b1, nullptr, h16);
    // Layers 2-3
    k_aggregate<<<gAgg, TPB>>>(h16, agg16);
    k_gemm_mma<true,false,true><<<gGemm, TPB>>>(agg16, W2h, b2, nullptr, h16);
    k_aggregate<<<gAgg, TPB>>>(h16, agg16);
    k_gemm_mma<true,false,true><<<gGemm, TPB>>>(agg16, W3h, b3, nullptr, h16);

    // Layer 4: aggregate, HMMA gemm + residual + relu (fp32 out), projection
    k_aggregate<<<gAgg, TPB>>>(h16, agg16);
    k_gemm_mma<true,true,false><<<gGemm, TPB>>>(agg16, W4h, b4, res, hA);
    k_gemm_out<<<gGemm, 128, OUT_SMEM>>>(hA, Wo, bo, out);
}